// round 12
// baseline (speedup 1.0000x reference)
#include <cuda_runtime.h>
#include <math.h>
#include <math_constants.h>

#define BATCH 4
#define DIM 256
#define IMG 32
#define NPOS 1024
#define HEADS 8
#define DHEAD 64
#define INNER 512
#define BH 32
#define SCALE 0.125f

// ---------------- scratch (device globals; no allocations) ----------------
static __device__ float d_xt[BATCH * DIM * NPOS];
static __device__ float d_xattn[BATCH * 2 * NPOS];
static __device__ float d_qm[BH * NPOS * 2];
static __device__ float d_km[BH * NPOS * 2];
static __device__ float d_mmax[BH * NPOS];
static __device__ float d_msum[BH * NPOS];
static __device__ int   d_top4[BH * NPOS * 4];
static __device__ float d_y[3 * BATCH * DIM * NPOS];
static __device__ float d_qh[BH * NPOS * DHEAD];
static __device__ float d_kh[BH * NPOS * DHEAD];
static __device__ float d_vh[BH * NPOS * DHEAD];
static __device__ float d_ao[BATCH * NPOS * INNER];

#define YSTRIDE (BATCH * DIM * NPOS)

// ---------------- packed f32x2 helpers ----------------
typedef unsigned long long u64r;
__device__ __forceinline__ u64r pk2(float lo, float hi) {
    u64r r; asm("mov.b64 %0, {%1, %2};" : "=l"(r) : "f"(lo), "f"(hi)); return r;
}
__device__ __forceinline__ void upk2(u64r v, float& lo, float& hi) {
    asm("mov.b64 {%0, %1}, %2;" : "=f"(lo), "=f"(hi) : "l"(v));
}
__device__ __forceinline__ void ffma2(u64r& d, u64r a, u64r b) {
    asm("fma.rn.f32x2 %0, %1, %2, %0;" : "+l"(d) : "l"(a), "l"(b));
}
__device__ __forceinline__ u64r fmul2(u64r a, u64r b) {
    u64r r; asm("mul.rn.f32x2 %0, %1, %2;" : "=l"(r) : "l"(a), "l"(b)); return r;
}

__device__ __forceinline__ float mask_logit(float qm0, float qm1, float km0, float km1) {
    return __fmul_rn(__fadd_rn(__fmul_rn(qm0, km0), __fmul_rn(qm1, km1)), SCALE);
}

// strict total order: value desc, index asc (lax.top_k tie-break)
__device__ __forceinline__ bool topgt(float v1, int j1, float v2, int j2) {
    return v1 > v2 || (v1 == v2 && j1 < j2);
}
__device__ __forceinline__ void ce_keepmax(float& va, int& ia, float vb, int ib) {
    bool t = topgt(vb, ib, va, ia);
    va = t ? vb : va; ia = t ? ib : ia;
}
__device__ __forceinline__ void ce_sort(float& va, int& ia, float& vb, int& ib) {
    bool t = topgt(vb, ib, va, ia);
    float v = t ? vb : va; int i = t ? ib : ia;
    vb = t ? va : vb; ib = t ? ia : ib;
    va = v; ia = i;
}

// ---------------- kernel 0: transpose ----------------
__global__ void k_transpose(const float* __restrict__ x) {
    __shared__ float tile[32][33];
    int b = blockIdx.z;
    int p0 = blockIdx.x * 32, c0 = blockIdx.y * 32;
    int tx = threadIdx.x, ty = threadIdx.y;
    #pragma unroll
    for (int r = 0; r < 32; r += 8)
        tile[ty + r][tx] = x[(b * NPOS + p0 + ty + r) * DIM + c0 + tx];
    __syncthreads();
    #pragma unroll
    for (int r = 0; r < 32; r += 8)
        d_xt[(b * DIM + c0 + ty + r) * NPOS + p0 + tx] = tile[tx][ty + r];
}

// ---------------- kernel 1: channel mean/max ----------------
__global__ void k_meanmax(const float* __restrict__ x) {
    int bp = blockIdx.x;
    int b = bp >> 10, p = bp & 1023;
    int tid = threadIdx.x;
    float v = x[(b * NPOS + p) * DIM + tid];
    __shared__ float ss[256], sm[256];
    ss[tid] = v; sm[tid] = v;
    __syncthreads();
    for (int s = 128; s > 0; s >>= 1) {
        if (tid < s) { ss[tid] += ss[tid + s]; sm[tid] = fmaxf(sm[tid], sm[tid + s]); }
        __syncthreads();
    }
    if (tid == 0) {
        d_xattn[b * 2 * NPOS + p] = ss[0] * (1.f / 256.f);
        d_xattn[b * 2 * NPOS + NPOS + p] = sm[0];
    }
}

// ---------------- kernel 2: mask 3x3 convs ----------------
__global__ void k_maskconv(const float* __restrict__ qmw, const float* __restrict__ qmb,
                           const float* __restrict__ kmw, const float* __restrict__ kmb) {
    int idx = blockIdx.x * 256 + threadIdx.x;
    int b = idx >> 14;
    int rem = idx & 16383;
    int oc = rem >> 10;
    int p = rem & 1023;
    int py = p >> 5, px = p & 31;
    float aq = 0.f, ak = 0.f;
    #pragma unroll
    for (int ic = 0; ic < 2; ic++) {
        const float* xa = &d_xattn[(b * 2 + ic) * NPOS];
        #pragma unroll
        for (int ky = 0; ky < 3; ky++) {
            int iy = py + ky - 1;
            if ((unsigned)iy >= 32u) continue;
            #pragma unroll
            for (int kx = 0; kx < 3; kx++) {
                int ix = px + kx - 1;
                if ((unsigned)ix >= 32u) continue;
                float xv = xa[iy * 32 + ix];
                aq = fmaf(xv, qmw[((oc * 2 + ic) * 3 + ky) * 3 + kx], aq);
                ak = fmaf(xv, kmw[((oc * 2 + ic) * 3 + ky) * 3 + kx], ak);
            }
        }
    }
    aq += qmb[oc]; ak += kmb[oc];
    int h = oc >> 1, dd = oc & 1;
    d_qm[((b * HEADS + h) * NPOS + p) * 2 + dd] = aq;
    d_km[((b * HEADS + h) * NPOS + p) * 2 + dd] = ak;
}

// ---------------- kernel 3: warp-per-row mask stats + top-4 ----------------
__global__ void k_masktop() {
    int tid = threadIdx.x;
    int w = tid >> 5, lane = tid & 31;
    int row0 = blockIdx.x * 8;
    int bh = row0 >> 10;
    __shared__ float2 km2[NPOS];
    const float2* kmsrc = (const float2*)&d_km[bh * NPOS * 2];
    #pragma unroll
    for (int t = 0; t < 4; t++) km2[t * 256 + tid] = kmsrc[t * 256 + tid];
    __syncthreads();

    int row = row0 + w;
    float2 q2 = ((const float2*)d_qm)[row];

    float v0 = -CUDART_INF_F, v1 = -CUDART_INF_F, v2 = -CUDART_INF_F, v3 = -CUDART_INF_F;
    int j0i = 0x7fffffff, j1i = 0x7fffffff, j2i = 0x7fffffff, j3i = 0x7fffffff;

    #pragma unroll
    for (int t = 0; t < 32; t++) {
        int j = t * 32 + lane;
        float2 k2 = km2[j];
        float l = mask_logit(q2.x, q2.y, k2.x, k2.y);
        bool g0 = l > v0;
        bool g1 = l > v1;
        bool g2 = l > v2;
        bool g3 = l > v3;
        float nv3 = g3 ? (g2 ? v2 : l) : v3; int nj3 = g3 ? (g2 ? j2i : j) : j3i;
        float nv2 = g2 ? (g1 ? v1 : l) : v2; int nj2 = g2 ? (g1 ? j1i : j) : j2i;
        float nv1 = g1 ? (g0 ? v0 : l) : v1; int nj1 = g1 ? (g0 ? j0i : j) : j1i;
        float nv0 = g0 ? l : v0;             int nj0 = g0 ? j : j0i;
        v0 = nv0; v1 = nv1; v2 = nv2; v3 = nv3;
        j0i = nj0; j1i = nj1; j2i = nj2; j3i = nj3;
    }

    #pragma unroll
    for (int off = 16; off > 0; off >>= 1) {
        float o0 = __shfl_xor_sync(0xffffffffu, v0, off);
        float o1 = __shfl_xor_sync(0xffffffffu, v1, off);
        float o2 = __shfl_xor_sync(0xffffffffu, v2, off);
        float o3 = __shfl_xor_sync(0xffffffffu, v3, off);
        int p0 = __shfl_xor_sync(0xffffffffu, j0i, off);
        int p1 = __shfl_xor_sync(0xffffffffu, j1i, off);
        int p2 = __shfl_xor_sync(0xffffffffu, j2i, off);
        int p3 = __shfl_xor_sync(0xffffffffu, j3i, off);
        ce_keepmax(v0, j0i, o3, p3);
        ce_keepmax(v1, j1i, o2, p2);
        ce_keepmax(v2, j2i, o1, p1);
        ce_keepmax(v3, j3i, o0, p0);
        ce_sort(v0, j0i, v2, j2i);
        ce_sort(v1, j1i, v3, j3i);
        ce_sort(v0, j0i, v1, j1i);
        ce_sort(v2, j2i, v3, j3i);
    }

    float m = v0;
    float s = 0.f;
    #pragma unroll
    for (int t = 0; t < 32; t++) {
        int j = t * 32 + lane;
        float2 k2 = km2[j];
        float l = mask_logit(q2.x, q2.y, k2.x, k2.y);
        s += __expf(l - m);
    }
    #pragma unroll
    for (int off = 16; off > 0; off >>= 1) s += __shfl_xor_sync(0xffffffffu, s, off);

    if (lane == 0) {
        d_mmax[row] = m;
        d_msum[row] = s;
        d_top4[row * 4 + 0] = j0i;
        d_top4[row * 4 + 1] = j1i;
        d_top4[row * 4 + 2] = j2i;
        d_top4[row * 4 + 3] = j3i;
    }
}

// ---------------- fused depthwise conv + BN (batch stats) + GELU ----------------
__global__ void k_sepconv(const float* __restrict__ w0, const float* __restrict__ b0,
                          const float* __restrict__ g0, const float* __restrict__ be0,
                          const float* __restrict__ w1, const float* __restrict__ b1,
                          const float* __restrict__ g1, const float* __restrict__ be1,
                          const float* __restrict__ w2, const float* __restrict__ b2,
                          const float* __restrict__ g2, const float* __restrict__ be2) {
    int c = blockIdx.x, br = blockIdx.y;
    const float* dw  = (br == 0) ? w0 : (br == 1) ? w1 : w2;
    const float* db  = (br == 0) ? b0 : (br == 1) ? b1 : b2;
    const float* gg  = (br == 0) ? g0 : (br == 1) ? g1 : g2;
    const float* bb  = (br == 0) ? be0 : (br == 1) ? be1 : be2;
    int tid = threadIdx.x;
    int lane = tid & 31, wid = tid >> 5;

    __shared__ float xs[BATCH][NPOS];
    __shared__ float w[9];
    __shared__ float bias;
    #pragma unroll
    for (int b = 0; b < BATCH; b++) {
        const float* src = &d_xt[(b * DIM + c) * NPOS];
        #pragma unroll
        for (int t = 0; t < 4; t++) xs[b][t * 256 + tid] = src[t * 256 + tid];
    }
    if (tid < 9) w[tid] = dw[c * 9 + tid];
    if (tid == 9) bias = db[c];
    __syncthreads();

    float vv[16];
    float s1 = 0.f, s2 = 0.f;
    #pragma unroll
    for (int b = 0; b < BATCH; b++) {
        #pragma unroll
        for (int t = 0; t < 4; t++) {
            int p = t * 256 + tid;
            int py = p >> 5, px = p & 31;
            float a = 0.f;
            #pragma unroll
            for (int ky = 0; ky < 3; ky++) {
                int iy = py + ky - 1;
                if ((unsigned)iy >= 32u) continue;
                #pragma unroll
                for (int kx = 0; kx < 3; kx++) {
                    int ix = px + kx - 1;
                    if ((unsigned)ix >= 32u) continue;
                    a = fmaf(xs[b][iy * 32 + ix], w[ky * 3 + kx], a);
                }
            }
            float v = a + bias;
            vv[b * 4 + t] = v;
            s1 += v;
            s2 = fmaf(v, v, s2);
        }
    }

    #pragma unroll
    for (int off = 16; off > 0; off >>= 1) {
        s1 += __shfl_xor_sync(0xffffffffu, s1, off);
        s2 += __shfl_xor_sync(0xffffffffu, s2, off);
    }
    __shared__ float rs1[8], rs2[8];
    if (lane == 0) { rs1[wid] = s1; rs2[wid] = s2; }
    __syncthreads();
    __shared__ float s_mu, s_var;
    if (tid == 0) {
        float a = 0.f, q = 0.f;
        #pragma unroll
        for (int i = 0; i < 8; i++) { a += rs1[i]; q += rs2[i]; }
        float mu = a * (1.f / 4096.f);
        float var = q * (1.f / 4096.f) - mu * mu;
        s_mu = mu;
        s_var = fmaxf(var, 0.f);
    }
    __syncthreads();

    float mu = s_mu, var = s_var;
    float gv = gg[c], bv = bb[c];
    float* dst = &d_y[br * YSTRIDE + c * NPOS];
    #pragma unroll
    for (int b = 0; b < BATCH; b++) {
        #pragma unroll
        for (int t = 0; t < 4; t++) {
            int p = t * 256 + tid;
            float nv = (vv[b * 4 + t] - mu) / sqrtf(var + 1e-5f) * gv + bv;
            float o = 0.5f * nv * (1.0f + erff(nv * 0.70710678118654752f));
            dst[b * DIM * NPOS + p] = o;
        }
    }
}

// ---------------- pointwise 1x1 conv GEMM (FFMA2, dup-W broadcast) ----------------
__global__ void k_pwgemm(const float* __restrict__ w0, const float* __restrict__ bb0,
                         const float* __restrict__ w1, const float* __restrict__ bb1,
                         const float* __restrict__ w2, const float* __restrict__ bb2) {
    __shared__ float As[32][68];
    __shared__ u64r Wsd[32][65];   // dup'd (w,w); reads are ty-broadcast (bank-immune)
    int br = blockIdx.z >> 2;
    int b = blockIdx.z & 3;
    const float* w = (br == 0) ? w0 : (br == 1) ? w1 : w2;
    const float* bias = (br == 0) ? bb0 : (br == 1) ? bb1 : bb2;
    float* out = (br == 0) ? d_qh : (br == 1) ? d_kh : d_vh;
    int oc0 = blockIdx.y * 64;
    int i0 = blockIdx.x * 64;
    int tid = threadIdx.x;
    int ty = tid >> 4, tx = tid & 15;
    u64r accp[4][2];
    #pragma unroll
    for (int r = 0; r < 4; r++) { accp[r][0] = 0ull; accp[r][1] = 0ull; }
    for (int c0 = 0; c0 < DIM; c0 += 32) {
        #pragma unroll
        for (int t = 0; t < 8; t++) {
            int idx = tid + t * 256;
            int ii = idx & 63, cc = idx >> 6;
            As[cc][ii] = d_y[br * YSTRIDE + (b * DIM + c0 + cc) * NPOS + i0 + ii];
        }
        #pragma unroll
        for (int t = 0; t < 8; t++) {
            int idx = tid + t * 256;
            int cc = idx & 31, o = idx >> 5;
            float wv = w[(oc0 + o) * DIM + c0 + cc];
            Wsd[cc][o] = pk2(wv, wv);
        }
        __syncthreads();
        #pragma unroll
        for (int cc = 0; cc < 32; cc++) {
            u64r a01 = *(const u64r*)&As[cc][tx * 4];
            u64r a23 = *(const u64r*)&As[cc][tx * 4 + 2];
            #pragma unroll
            for (int r = 0; r < 4; r++) {
                u64r ww = Wsd[cc][ty * 4 + r];
                ffma2(accp[r][0], a01, ww);
                ffma2(accp[r][1], a23, ww);
            }
        }
        __syncthreads();
    }
    #pragma unroll
    for (int r = 0; r < 4; r++) {
        int oc = oc0 + ty * 4 + r;
        int h = oc >> 6, dd = oc & 63;
        float bbv = bias[oc];
        float c0v, c1v, c2v, c3v;
        upk2(accp[r][0], c0v, c1v);
        upk2(accp[r][1], c2v, c3v);
        float cv[4] = {c0v, c1v, c2v, c3v};
        #pragma unroll
        for (int cq = 0; cq < 4; cq++) {
            int ii = i0 + tx * 4 + cq;
            out[((b * HEADS + h) * NPOS + ii) * DHEAD + dd] = cv[cq] + bbv;
        }
    }
}

// ---------------- fused attention (FFMA2, dup-E PV, dynamic smem, one wave) ----------------
#define QS_OFF   0                           // float[64][68] = 17408
#define KS_OFF   17408                       // float[64][33] = 8448
#define VS_OFF   25856                       // float[32][68] = 8704
#define ESD_OFF  34560                       // u64[32][65]   = 16640 (8B aligned)
#define QM_OFF   51200                       // float[64][2]  = 512
#define MMAX_OFF 51712                       // float[64]     = 256
#define MINV_OFF 51968                       // float[64]     = 256
#define TOP_OFF  52224                       // int[64][4]    = 1024
#define SMEM_ATTN 53248

__global__ void __launch_bounds__(256, 4) k_attn() {
    extern __shared__ char smraw[];
    float (*Qs)[68]   = (float(*)[68])(smraw + QS_OFF);
    float (*Ks)[33]   = (float(*)[33])(smraw + KS_OFF);
    float (*Vs)[68]   = (float(*)[68])(smraw + VS_OFF);
    u64r  (*Esd)[65]  = (u64r(*)[65])(smraw + ESD_OFF);
    float (*s_qm)[2]  = (float(*)[2])(smraw + QM_OFF);
    float* s_mmax     = (float*)(smraw + MMAX_OFF);
    float* s_minv     = (float*)(smraw + MINV_OFF);
    int   (*s_top)[4] = (int(*)[4])(smraw + TOP_OFF);

    int i0 = blockIdx.x * 64;
    int bh = blockIdx.y;
    int tid = threadIdx.x;
    int ty = tid >> 4, tx = tid & 15;

    #pragma unroll
    for (int t = 0; t < 16; t++) {
        int idx = tid + t * 256;
        int dd = idx & 63, ii = idx >> 6;
        Qs[dd][ii] = d_qh[(bh * NPOS + i0 + ii) * DHEAD + dd];
    }
    if (tid < 64) {
        int ig = bh * NPOS + i0 + tid;
        s_qm[tid][0] = d_qm[ig * 2];
        s_qm[tid][1] = d_qm[ig * 2 + 1];
        s_mmax[tid] = d_mmax[ig];
        s_minv[tid] = 1.0f / d_msum[ig];
        #pragma unroll
        for (int t = 0; t < 4; t++) s_top[tid][t] = d_top4[ig * 4 + t];
    }
    __syncthreads();

    float run_max[4], run_sum[4];
    #pragma unroll
    for (int r = 0; r < 4; r++) { run_max[r] = -CUDART_INF_F; run_sum[r] = 0.f; }
    // PV accum: accp[r][cp] = row ty*4+r, cols (tx*4+2cp, tx*4+2cp+1)
    u64r accp[4][2];
    #pragma unroll
    for (int r = 0; r < 4; r++) { accp[r][0] = 0ull; accp[r][1] = 0ull; }

    for (int j0 = 0; j0 < NPOS; j0 += 32) {
        #pragma unroll
        for (int t = 0; t < 8; t++) {
            int idx = tid + t * 256;
            int dd = idx & 63, jj = idx >> 6;
            Ks[dd][jj] = d_kh[(bh * NPOS + j0 + jj) * DHEAD + dd];
            Vs[jj][dd] = d_vh[(bh * NPOS + j0 + jj) * DHEAD + dd];
        }
        __syncthreads();

        // QK: row-paired accumulators, scalar-K dup via pack
        u64r q00 = 0ull, q01 = 0ull, q10 = 0ull, q11 = 0ull;
        #pragma unroll
        for (int dd = 0; dd < 64; dd++) {
            u64r a01 = *(const u64r*)&Qs[dd][ty * 4];
            u64r a23 = *(const u64r*)&Qs[dd][ty * 4 + 2];
            float b0 = Ks[dd][tx * 2];
            float b1 = Ks[dd][tx * 2 + 1];
            u64r bb0 = pk2(b0, b0);
            u64r bb1 = pk2(b1, b1);
            ffma2(q00, a01, bb0);
            ffma2(q01, a01, bb1);
            ffma2(q10, a23, bb0);
            ffma2(q11, a23, bb1);
        }
        float sv[8];
        upk2(q00, sv[0], sv[2]);
        upk2(q01, sv[1], sv[3]);
        upk2(q10, sv[4], sv[6]);
        upk2(q11, sv[5], sv[7]);

        // mask epilogue
        #pragma unroll
        for (int cq = 0; cq < 2; cq++) {
            int jg = j0 + tx * 2 + cq;
            float2 k2 = ((const float2*)d_km)[bh * NPOS + jg];
            #pragma unroll
            for (int r = 0; r < 4; r++) {
                int il = ty * 4 + r;
                float ml = mask_logit(s_qm[il][0], s_qm[il][1], k2.x, k2.y);
                float dprob = __expf(ml - s_mmax[il]) * s_minv[il];
                float oneh = (jg == s_top[il][0] || jg == s_top[il][1] ||
                              jg == s_top[il][2] || jg == s_top[il][3]) ? 1.0f : -100000.0f;
                float maskv = __fadd_rn(__fadd_rn(oneh, -dprob), dprob);
                sv[r * 2 + cq] = __fmul_rn(__fmul_rn(sv[r * 2 + cq], SCALE), maskv);
            }
        }

        // tile row max across the 16-lane half-warp
        float tm[4];
        #pragma unroll
        for (int r = 0; r < 4; r++) tm[r] = fmaxf(sv[r * 2], sv[r * 2 + 1]);
        #pragma unroll
        for (int off = 1; off < 16; off <<= 1) {
            #pragma unroll
            for (int r = 0; r < 4; r++)
                tm[r] = fmaxf(tm[r], __shfl_xor_sync(0xffffffffu, tm[r], off));
        }

        // online softmax update + dup-E store + acc rescale
        float fr[4];
        #pragma unroll
        for (int r = 0; r < 4; r++) {
            float nm = fmaxf(run_max[r], tm[r]);
            float f = __expf(run_max[r] - nm);   // 0 on first tile
            run_max[r] = nm;
            fr[r] = f;
            float e0 = __expf(sv[r * 2] - nm);
            float e1 = __expf(sv[r * 2 + 1] - nm);
            run_sum[r] = run_sum[r] * f + e0 + e1;
            Esd[tx * 2][ty * 4 + r]     = pk2(e0, e0);
            Esd[tx * 2 + 1][ty * 4 + r] = pk2(e1, e1);
        }
        #pragma unroll
        for (int r = 0; r < 4; r++) {
            u64r ffr = pk2(fr[r], fr[r]);
            accp[r][0] = fmul2(accp[r][0], ffr);
            accp[r][1] = fmul2(accp[r][1], ffr);
        }
        __syncthreads();

        // PV: dup-E broadcast reads (bank-immune), natural V LDS.64 pairs
        #pragma unroll
        for (int jj = 0; jj < 32; jj++) {
            u64r b0 = *(const u64r*)&Vs[jj][tx * 4];
            u64r b1 = *(const u64r*)&Vs[jj][tx * 4 + 2];
            #pragma unroll
            for (int r = 0; r < 4; r++) {
                u64r a = Esd[jj][ty * 4 + r];
                ffma2(accp[r][0], a, b0);
                ffma2(accp[r][1], a, b1);
            }
        }
        __syncthreads();
    }

    #pragma unroll
    for (int off = 1; off < 16; off <<= 1) {
        #pragma unroll
        for (int r = 0; r < 4; r++)
            run_sum[r] += __shfl_xor_sync(0xffffffffu, run_sum[r], off);
    }

    int b = bh >> 3, h = bh & 7;
    #pragma unroll
    for (int r = 0; r < 4; r++) {
        int ii = i0 + ty * 4 + r;
        float inv = 1.0f / run_sum[r];
        float o0v, o1v, o2v, o3v;
        upk2(accp[r][0], o0v, o1v);
        upk2(accp[r][1], o2v, o3v);
        float4 st;
        st.x = o0v * inv; st.y = o1v * inv; st.z = o2v * inv; st.w = o3v * inv;
        *(float4*)&d_ao[((size_t)(b * NPOS + ii)) * INNER + h * DHEAD + tx * 4] = st;
    }
}

// ---------------- output GEMM (FFMA2) ----------------
__global__ void k_out(const float* __restrict__ w, const float* __restrict__ ob, float* __restrict__ out) {
    __shared__ float As[32][68];
    __shared__ float Ws[32][68];
    int o0 = blockIdx.x * 64;
    int bi0 = blockIdx.y * 64;
    int tid = threadIdx.x;
    int ty = tid >> 4, tx = tid & 15;
    u64r accp[4][2];
    #pragma unroll
    for (int r = 0; r < 4; r++) { accp[r][0] = 0ull; accp[r][1] = 0ull; }
    for (int c0 = 0; c0 < INNER; c0 += 32) {
        #pragma unroll
        for (int t = 0; t < 8; t++) {
            int idx = tid + t * 256;
            int cc = idx & 31, ii = idx >> 5;
            As[cc][ii] = d_ao[(size_t)(bi0 + ii) * INNER + c0 + cc];
        }
        #pragma unroll
        for (int t = 0; t < 8; t++) {
            int idx = tid + t * 256;
            int cc = idx & 31, o = idx >> 5;
            Ws[cc][o] = w[(o0 + o) * INNER + c0 + cc];
        }
        __syncthreads();
        #pragma unroll
        for (int cc = 0; cc < 32; cc++) {
            u64r a01 = *(const u64r*)&As[cc][ty * 4];
            u64r a23 = *(const u64r*)&As[cc][ty * 4 + 2];
            #pragma unroll
            for (int r = 0; r < 4; r++) {
                float wv = Ws[cc][tx * 4 + r];
                u64r ww = pk2(wv, wv);
                ffma2(accp[r][0], a01, ww);
                ffma2(accp[r][1], a23, ww);
            }
        }
        __syncthreads();
    }
    #pragma unroll
    for (int r = 0; r < 4; r++) {
        int o = o0 + tx * 4 + r;
        float b0v, b1v, b2v, b3v;
        upk2(accp[r][0], b0v, b1v);
        upk2(accp[r][1], b2v, b3v);
        float bv[4] = {b0v, b1v, b2v, b3v};
        float obv = ob[o];
        #pragma unroll
        for (int q = 0; q < 4; q++) {
            int bi = bi0 + ty * 4 + q;
            out[(size_t)bi * DIM + o] = bv[q] + obv;
        }
    }
}

// ---------------- launch ----------------
extern "C" void kernel_launch(void* const* d_in, const int* in_sizes, int n_in,
                              void* d_out, int out_size) {
    const float* x     = (const float*)d_in[0];
    const float* qd_w  = (const float*)d_in[1];
    const float* qd_b  = (const float*)d_in[2];
    const float* q_g   = (const float*)d_in[3];
    const float* q_be  = (const float*)d_in[4];
    const float* qp_w  = (const float*)d_in[5];
    const float* qp_b  = (const float*)d_in[6];
    const float* qm_w  = (const float*)d_in[7];
    const float* qm_b  = (const float*)d_in[8];
    const float* kd_w  = (const float*)d_in[9];
    const float* kd_b  = (const float*)d_in[10];
    const float* k_g   = (const float*)d_in[11];
    const float* k_be  = (const float*)d_in[12];
    const float* kp_w  = (const float*)d_in[13];
    const float* kp_b  = (const float*)d_in[14];
    const float* km_w  = (const float*)d_in[15];
    const float* km_b  = (const float*)d_in[16];
    const float* vd_w  = (const float*)d_in[17];
    const float* vd_b  = (const float*)d_in[18];
    const float* v_g   = (const float*)d_in[19];
    const float* v_be  = (const float*)d_in[20];
    const float* vp_w  = (const float*)d_in[21];
    const float* vp_b  = (const float*)d_in[22];
    const float* out_w = (const float*)d_in[25];
    const float* out_b = (const float*)d_in[26];
    float* out = (float*)d_out;

    // unconditional (idempotent, capture-legal)
    cudaFuncSetAttribute(k_attn, cudaFuncAttributeMaxDynamicSharedMemorySize, SMEM_ATTN);

    k_transpose<<<dim3(32, 8, 4), dim3(32, 8)>>>(x);
    k_meanmax<<<4096, 256>>>(x);
    k_maskconv<<<256, 256>>>(qm_w, qm_b, km_w, km_b);
    k_masktop<<<4096, 256>>>();

    k_sepconv<<<dim3(256, 3), 256>>>(qd_w, qd_b, q_g, q_be,
                                     kd_w, kd_b, k_g, k_be,
                                     vd_w, vd_b, v_g, v_be);
    k_pwgemm<<<dim3(16, 8, 12), 256>>>(qp_w, qp_b, kp_w, kp_b, vp_w, vp_b);

    k_attn<<<dim3(16, 32), 256, SMEM_ATTN>>>();
    k_out<<<dim3(4, 64), 256>>>(out_w, out_b, out);
}

// round 13
// speedup vs baseline: 1.0854x; 1.0854x over previous
#include <cuda_runtime.h>
#include <math.h>
#include <math_constants.h>

#define BATCH 4
#define DIM 256
#define IMG 32
#define NPOS 1024
#define HEADS 8
#define DHEAD 64
#define INNER 512
#define BH 32
#define SCALE 0.125f

// ---------------- scratch (device globals; no allocations) ----------------
static __device__ float d_xt[BATCH * DIM * NPOS];
static __device__ float d_xattn[BATCH * 2 * NPOS];
static __device__ float d_qm[BH * NPOS * 2];
static __device__ float d_km[BH * NPOS * 2];
static __device__ float d_mmax[BH * NPOS];
static __device__ float d_msum[BH * NPOS];
static __device__ int   d_top4[BH * NPOS * 4];
static __device__ float d_y[3 * BATCH * DIM * NPOS];
static __device__ float d_qh[BH * NPOS * DHEAD];
static __device__ float d_kh[BH * NPOS * DHEAD];
static __device__ float d_vh[BH * NPOS * DHEAD];
static __device__ float d_ao[BATCH * NPOS * INNER];

#define YSTRIDE (BATCH * DIM * NPOS)

// ---------------- packed f32x2 helpers ----------------
typedef unsigned long long u64r;
__device__ __forceinline__ u64r pk2(float lo, float hi) {
    u64r r; asm("mov.b64 %0, {%1, %2};" : "=l"(r) : "f"(lo), "f"(hi)); return r;
}
__device__ __forceinline__ void upk2(u64r v, float& lo, float& hi) {
    asm("mov.b64 {%0, %1}, %2;" : "=f"(lo), "=f"(hi) : "l"(v));
}
__device__ __forceinline__ void ffma2(u64r& d, u64r a, u64r b) {
    asm("fma.rn.f32x2 %0, %1, %2, %0;" : "+l"(d) : "l"(a), "l"(b));
}
__device__ __forceinline__ u64r fmul2(u64r a, u64r b) {
    u64r r; asm("mul.rn.f32x2 %0, %1, %2;" : "=l"(r) : "l"(a), "l"(b)); return r;
}

__device__ __forceinline__ float mask_logit(float qm0, float qm1, float km0, float km1) {
    return __fmul_rn(__fadd_rn(__fmul_rn(qm0, km0), __fmul_rn(qm1, km1)), SCALE);
}

// strict total order: value desc, index asc (lax.top_k tie-break)
__device__ __forceinline__ bool topgt(float v1, int j1, float v2, int j2) {
    return v1 > v2 || (v1 == v2 && j1 < j2);
}
__device__ __forceinline__ void ce_keepmax(float& va, int& ia, float vb, int ib) {
    bool t = topgt(vb, ib, va, ia);
    va = t ? vb : va; ia = t ? ib : ia;
}
__device__ __forceinline__ void ce_sort(float& va, int& ia, float& vb, int& ib) {
    bool t = topgt(vb, ib, va, ia);
    float v = t ? vb : va; int i = t ? ib : ia;
    vb = t ? va : vb; ib = t ? ia : ib;
    va = v; ia = i;
}

// ---------------- kernel 0: transpose ----------------
__global__ void k_transpose(const float* __restrict__ x) {
    __shared__ float tile[32][33];
    int b = blockIdx.z;
    int p0 = blockIdx.x * 32, c0 = blockIdx.y * 32;
    int tx = threadIdx.x, ty = threadIdx.y;
    #pragma unroll
    for (int r = 0; r < 32; r += 8)
        tile[ty + r][tx] = x[(b * NPOS + p0 + ty + r) * DIM + c0 + tx];
    __syncthreads();
    #pragma unroll
    for (int r = 0; r < 32; r += 8)
        d_xt[(b * DIM + c0 + ty + r) * NPOS + p0 + tx] = tile[tx][ty + r];
}

// ---------------- kernel 1: channel mean/max ----------------
__global__ void k_meanmax(const float* __restrict__ x) {
    int bp = blockIdx.x;
    int b = bp >> 10, p = bp & 1023;
    int tid = threadIdx.x;
    float v = x[(b * NPOS + p) * DIM + tid];
    __shared__ float ss[256], sm[256];
    ss[tid] = v; sm[tid] = v;
    __syncthreads();
    for (int s = 128; s > 0; s >>= 1) {
        if (tid < s) { ss[tid] += ss[tid + s]; sm[tid] = fmaxf(sm[tid], sm[tid + s]); }
        __syncthreads();
    }
    if (tid == 0) {
        d_xattn[b * 2 * NPOS + p] = ss[0] * (1.f / 256.f);
        d_xattn[b * 2 * NPOS + NPOS + p] = sm[0];
    }
}

// ---------------- kernel 2: mask 3x3 convs ----------------
__global__ void k_maskconv(const float* __restrict__ qmw, const float* __restrict__ qmb,
                           const float* __restrict__ kmw, const float* __restrict__ kmb) {
    int idx = blockIdx.x * 256 + threadIdx.x;
    int b = idx >> 14;
    int rem = idx & 16383;
    int oc = rem >> 10;
    int p = rem & 1023;
    int py = p >> 5, px = p & 31;
    float aq = 0.f, ak = 0.f;
    #pragma unroll
    for (int ic = 0; ic < 2; ic++) {
        const float* xa = &d_xattn[(b * 2 + ic) * NPOS];
        #pragma unroll
        for (int ky = 0; ky < 3; ky++) {
            int iy = py + ky - 1;
            if ((unsigned)iy >= 32u) continue;
            #pragma unroll
            for (int kx = 0; kx < 3; kx++) {
                int ix = px + kx - 1;
                if ((unsigned)ix >= 32u) continue;
                float xv = xa[iy * 32 + ix];
                aq = fmaf(xv, qmw[((oc * 2 + ic) * 3 + ky) * 3 + kx], aq);
                ak = fmaf(xv, kmw[((oc * 2 + ic) * 3 + ky) * 3 + kx], ak);
            }
        }
    }
    aq += qmb[oc]; ak += kmb[oc];
    int h = oc >> 1, dd = oc & 1;
    d_qm[((b * HEADS + h) * NPOS + p) * 2 + dd] = aq;
    d_km[((b * HEADS + h) * NPOS + p) * 2 + dd] = ak;
}

// ---------------- kernel 3: warp-per-row mask stats + top-4 ----------------
__global__ void k_masktop() {
    int tid = threadIdx.x;
    int w = tid >> 5, lane = tid & 31;
    int row0 = blockIdx.x * 8;
    int bh = row0 >> 10;
    __shared__ float2 km2[NPOS];
    const float2* kmsrc = (const float2*)&d_km[bh * NPOS * 2];
    #pragma unroll
    for (int t = 0; t < 4; t++) km2[t * 256 + tid] = kmsrc[t * 256 + tid];
    __syncthreads();

    int row = row0 + w;
    float2 q2 = ((const float2*)d_qm)[row];

    float v0 = -CUDART_INF_F, v1 = -CUDART_INF_F, v2 = -CUDART_INF_F, v3 = -CUDART_INF_F;
    int j0i = 0x7fffffff, j1i = 0x7fffffff, j2i = 0x7fffffff, j3i = 0x7fffffff;

    #pragma unroll
    for (int t = 0; t < 32; t++) {
        int j = t * 32 + lane;
        float2 k2 = km2[j];
        float l = mask_logit(q2.x, q2.y, k2.x, k2.y);
        bool g0 = l > v0;
        bool g1 = l > v1;
        bool g2 = l > v2;
        bool g3 = l > v3;
        float nv3 = g3 ? (g2 ? v2 : l) : v3; int nj3 = g3 ? (g2 ? j2i : j) : j3i;
        float nv2 = g2 ? (g1 ? v1 : l) : v2; int nj2 = g2 ? (g1 ? j1i : j) : j2i;
        float nv1 = g1 ? (g0 ? v0 : l) : v1; int nj1 = g1 ? (g0 ? j0i : j) : j1i;
        float nv0 = g0 ? l : v0;             int nj0 = g0 ? j : j0i;
        v0 = nv0; v1 = nv1; v2 = nv2; v3 = nv3;
        j0i = nj0; j1i = nj1; j2i = nj2; j3i = nj3;
    }

    #pragma unroll
    for (int off = 16; off > 0; off >>= 1) {
        float o0 = __shfl_xor_sync(0xffffffffu, v0, off);
        float o1 = __shfl_xor_sync(0xffffffffu, v1, off);
        float o2 = __shfl_xor_sync(0xffffffffu, v2, off);
        float o3 = __shfl_xor_sync(0xffffffffu, v3, off);
        int p0 = __shfl_xor_sync(0xffffffffu, j0i, off);
        int p1 = __shfl_xor_sync(0xffffffffu, j1i, off);
        int p2 = __shfl_xor_sync(0xffffffffu, j2i, off);
        int p3 = __shfl_xor_sync(0xffffffffu, j3i, off);
        ce_keepmax(v0, j0i, o3, p3);
        ce_keepmax(v1, j1i, o2, p2);
        ce_keepmax(v2, j2i, o1, p1);
        ce_keepmax(v3, j3i, o0, p0);
        ce_sort(v0, j0i, v2, j2i);
        ce_sort(v1, j1i, v3, j3i);
        ce_sort(v0, j0i, v1, j1i);
        ce_sort(v2, j2i, v3, j3i);
    }

    float m = v0;
    float s = 0.f;
    #pragma unroll
    for (int t = 0; t < 32; t++) {
        int j = t * 32 + lane;
        float2 k2 = km2[j];
        float l = mask_logit(q2.x, q2.y, k2.x, k2.y);
        s += __expf(l - m);
    }
    #pragma unroll
    for (int off = 16; off > 0; off >>= 1) s += __shfl_xor_sync(0xffffffffu, s, off);

    if (lane == 0) {
        d_mmax[row] = m;
        d_msum[row] = s;
        d_top4[row * 4 + 0] = j0i;
        d_top4[row * 4 + 1] = j1i;
        d_top4[row * 4 + 2] = j2i;
        d_top4[row * 4 + 3] = j3i;
    }
}

// ---------------- fused depthwise conv + BN (batch stats) + GELU ----------------
__global__ void k_sepconv(const float* __restrict__ w0, const float* __restrict__ b0,
                          const float* __restrict__ g0, const float* __restrict__ be0,
                          const float* __restrict__ w1, const float* __restrict__ b1,
                          const float* __restrict__ g1, const float* __restrict__ be1,
                          const float* __restrict__ w2, const float* __restrict__ b2,
                          const float* __restrict__ g2, const float* __restrict__ be2) {
    int c = blockIdx.x, br = blockIdx.y;
    const float* dw  = (br == 0) ? w0 : (br == 1) ? w1 : w2;
    const float* db  = (br == 0) ? b0 : (br == 1) ? b1 : b2;
    const float* gg  = (br == 0) ? g0 : (br == 1) ? g1 : g2;
    const float* bb  = (br == 0) ? be0 : (br == 1) ? be1 : be2;
    int tid = threadIdx.x;
    int lane = tid & 31, wid = tid >> 5;

    __shared__ float xs[BATCH][NPOS];
    __shared__ float w[9];
    __shared__ float bias;
    #pragma unroll
    for (int b = 0; b < BATCH; b++) {
        const float* src = &d_xt[(b * DIM + c) * NPOS];
        #pragma unroll
        for (int t = 0; t < 4; t++) xs[b][t * 256 + tid] = src[t * 256 + tid];
    }
    if (tid < 9) w[tid] = dw[c * 9 + tid];
    if (tid == 9) bias = db[c];
    __syncthreads();

    float vv[16];
    float s1 = 0.f, s2 = 0.f;
    #pragma unroll
    for (int b = 0; b < BATCH; b++) {
        #pragma unroll
        for (int t = 0; t < 4; t++) {
            int p = t * 256 + tid;
            int py = p >> 5, px = p & 31;
            float a = 0.f;
            #pragma unroll
            for (int ky = 0; ky < 3; ky++) {
                int iy = py + ky - 1;
                if ((unsigned)iy >= 32u) continue;
                #pragma unroll
                for (int kx = 0; kx < 3; kx++) {
                    int ix = px + kx - 1;
                    if ((unsigned)ix >= 32u) continue;
                    a = fmaf(xs[b][iy * 32 + ix], w[ky * 3 + kx], a);
                }
            }
            float v = a + bias;
            vv[b * 4 + t] = v;
            s1 += v;
            s2 = fmaf(v, v, s2);
        }
    }

    #pragma unroll
    for (int off = 16; off > 0; off >>= 1) {
        s1 += __shfl_xor_sync(0xffffffffu, s1, off);
        s2 += __shfl_xor_sync(0xffffffffu, s2, off);
    }
    __shared__ float rs1[8], rs2[8];
    if (lane == 0) { rs1[wid] = s1; rs2[wid] = s2; }
    __syncthreads();
    __shared__ float s_mu, s_var;
    if (tid == 0) {
        float a = 0.f, q = 0.f;
        #pragma unroll
        for (int i = 0; i < 8; i++) { a += rs1[i]; q += rs2[i]; }
        float mu = a * (1.f / 4096.f);
        float var = q * (1.f / 4096.f) - mu * mu;
        s_mu = mu;
        s_var = fmaxf(var, 0.f);
    }
    __syncthreads();

    float mu = s_mu, var = s_var;
    float gv = gg[c], bv = bb[c];
    float* dst = &d_y[br * YSTRIDE + c * NPOS];
    #pragma unroll
    for (int b = 0; b < BATCH; b++) {
        #pragma unroll
        for (int t = 0; t < 4; t++) {
            int p = t * 256 + tid;
            float nv = (vv[b * 4 + t] - mu) / sqrtf(var + 1e-5f) * gv + bv;
            float o = 0.5f * nv * (1.0f + erff(nv * 0.70710678118654752f));
            dst[b * DIM * NPOS + p] = o;
        }
    }
}

// ---------------- pointwise 1x1 conv GEMM (FFMA2, dup-W broadcast) ----------------
__global__ void k_pwgemm(const float* __restrict__ w0, const float* __restrict__ bb0,
                         const float* __restrict__ w1, const float* __restrict__ bb1,
                         const float* __restrict__ w2, const float* __restrict__ bb2) {
    __shared__ float As[32][68];
    __shared__ u64r Wsd[32][65];   // dup'd (w,w); reads are ty-broadcast (bank-immune)
    int br = blockIdx.z >> 2;
    int b = blockIdx.z & 3;
    const float* w = (br == 0) ? w0 : (br == 1) ? w1 : w2;
    const float* bias = (br == 0) ? bb0 : (br == 1) ? bb1 : bb2;
    float* out = (br == 0) ? d_qh : (br == 1) ? d_kh : d_vh;
    int oc0 = blockIdx.y * 64;
    int i0 = blockIdx.x * 64;
    int tid = threadIdx.x;
    int ty = tid >> 4, tx = tid & 15;
    u64r accp[4][2];
    #pragma unroll
    for (int r = 0; r < 4; r++) { accp[r][0] = 0ull; accp[r][1] = 0ull; }
    for (int c0 = 0; c0 < DIM; c0 += 32) {
        #pragma unroll
        for (int t = 0; t < 8; t++) {
            int idx = tid + t * 256;
            int ii = idx & 63, cc = idx >> 6;
            As[cc][ii] = d_y[br * YSTRIDE + (b * DIM + c0 + cc) * NPOS + i0 + ii];
        }
        #pragma unroll
        for (int t = 0; t < 8; t++) {
            int idx = tid + t * 256;
            int cc = idx & 31, o = idx >> 5;
            float wv = w[(oc0 + o) * DIM + c0 + cc];
            Wsd[cc][o] = pk2(wv, wv);
        }
        __syncthreads();
        #pragma unroll
        for (int cc = 0; cc < 32; cc++) {
            u64r a01 = *(const u64r*)&As[cc][tx * 4];
            u64r a23 = *(const u64r*)&As[cc][tx * 4 + 2];
            #pragma unroll
            for (int r = 0; r < 4; r++) {
                u64r ww = Wsd[cc][ty * 4 + r];
                ffma2(accp[r][0], a01, ww);
                ffma2(accp[r][1], a23, ww);
            }
        }
        __syncthreads();
    }
    #pragma unroll
    for (int r = 0; r < 4; r++) {
        int oc = oc0 + ty * 4 + r;
        int h = oc >> 6, dd = oc & 63;
        float bbv = bias[oc];
        float c0v, c1v, c2v, c3v;
        upk2(accp[r][0], c0v, c1v);
        upk2(accp[r][1], c2v, c3v);
        float cv[4] = {c0v, c1v, c2v, c3v};
        #pragma unroll
        for (int cq = 0; cq < 4; cq++) {
            int ii = i0 + tx * 4 + cq;
            out[((b * HEADS + h) * NPOS + ii) * DHEAD + dd] = cv[cq] + bbv;
        }
    }
}

// ---------------- fused attention (FFMA2): QK*mask -> online softmax -> PV ----------------
__global__ void k_attn() {
    __shared__ float Qs[64][68];    // [dd][ii]
    __shared__ float Ks[64][33];    // [dd][jj]
    __shared__ float Vs[32][68];    // [jj][dd]
    __shared__ float Es[32][68];    // [jj][ii]
    __shared__ float s_qm[64][2];
    __shared__ float s_mmax[64];
    __shared__ float s_minv[64];
    __shared__ int   s_top[64][4];

    int i0 = blockIdx.x * 64;
    int bh = blockIdx.y;
    int tid = threadIdx.x;
    int ty = tid >> 4, tx = tid & 15;

    #pragma unroll
    for (int t = 0; t < 16; t++) {
        int idx = tid + t * 256;
        int dd = idx & 63, ii = idx >> 6;
        Qs[dd][ii] = d_qh[(bh * NPOS + i0 + ii) * DHEAD + dd];
    }
    if (tid < 64) {
        int ig = bh * NPOS + i0 + tid;
        s_qm[tid][0] = d_qm[ig * 2];
        s_qm[tid][1] = d_qm[ig * 2 + 1];
        s_mmax[tid] = d_mmax[ig];
        s_minv[tid] = 1.0f / d_msum[ig];
        #pragma unroll
        for (int t = 0; t < 4; t++) s_top[tid][t] = d_top4[ig * 4 + t];
    }
    __syncthreads();

    float run_max[4], run_sum[4];
    #pragma unroll
    for (int r = 0; r < 4; r++) { run_max[r] = -CUDART_INF_F; run_sum[r] = 0.f; }
    u64r accp[2][4];
    #pragma unroll
    for (int c = 0; c < 4; c++) { accp[0][c] = 0ull; accp[1][c] = 0ull; }

    for (int j0 = 0; j0 < NPOS; j0 += 32) {
        #pragma unroll
        for (int t = 0; t < 8; t++) {
            int idx = tid + t * 256;
            int dd = idx & 63, jj = idx >> 6;
            Ks[dd][jj] = d_kh[(bh * NPOS + j0 + jj) * DHEAD + dd];
            Vs[jj][dd] = d_vh[(bh * NPOS + j0 + jj) * DHEAD + dd];
        }
        __syncthreads();

        u64r q00 = 0ull, q01 = 0ull, q10 = 0ull, q11 = 0ull;
        #pragma unroll
        for (int dd = 0; dd < 64; dd++) {
            u64r a01 = *(const u64r*)&Qs[dd][ty * 4];
            u64r a23 = *(const u64r*)&Qs[dd][ty * 4 + 2];
            float b0 = Ks[dd][tx * 2];
            float b1 = Ks[dd][tx * 2 + 1];
            u64r bb0 = pk2(b0, b0);
            u64r bb1 = pk2(b1, b1);
            ffma2(q00, a01, bb0);
            ffma2(q01, a01, bb1);
            ffma2(q10, a23, bb0);
            ffma2(q11, a23, bb1);
        }
        float sv[8];
        upk2(q00, sv[0], sv[2]);
        upk2(q01, sv[1], sv[3]);
        upk2(q10, sv[4], sv[6]);
        upk2(q11, sv[5], sv[7]);

        #pragma unroll
        for (int cq = 0; cq < 2; cq++) {
            int jg = j0 + tx * 2 + cq;
            float2 k2 = ((const float2*)d_km)[bh * NPOS + jg];
            #pragma unroll
            for (int r = 0; r < 4; r++) {
                int il = ty * 4 + r;
                float ml = mask_logit(s_qm[il][0], s_qm[il][1], k2.x, k2.y);
                float dprob = __expf(ml - s_mmax[il]) * s_minv[il];
                float oneh = (jg == s_top[il][0] || jg == s_top[il][1] ||
                              jg == s_top[il][2] || jg == s_top[il][3]) ? 1.0f : -100000.0f;
                float maskv = __fadd_rn(__fadd_rn(oneh, -dprob), dprob);
                sv[r * 2 + cq] = __fmul_rn(__fmul_rn(sv[r * 2 + cq], SCALE), maskv);
            }
        }

        float tm[4];
        #pragma unroll
        for (int r = 0; r < 4; r++) tm[r] = fmaxf(sv[r * 2], sv[r * 2 + 1]);
        #pragma unroll
        for (int off = 1; off < 16; off <<= 1) {
            #pragma unroll
            for (int r = 0; r < 4; r++)
                tm[r] = fmaxf(tm[r], __shfl_xor_sync(0xffffffffu, tm[r], off));
        }

        float fr[4];
        #pragma unroll
        for (int r = 0; r < 4; r++) {
            float nm = fmaxf(run_max[r], tm[r]);
            float f = __expf(run_max[r] - nm);
            run_max[r] = nm;
            fr[r] = f;
            float e0 = __expf(sv[r * 2] - nm);
            float e1 = __expf(sv[r * 2 + 1] - nm);
            run_sum[r] = run_sum[r] * f + e0 + e1;
            Es[tx * 2][ty * 4 + r]     = e0;
            Es[tx * 2 + 1][ty * 4 + r] = e1;
        }
        {
            u64r ff0 = pk2(fr[0], fr[1]);
            u64r ff1 = pk2(fr[2], fr[3]);
            #pragma unroll
            for (int c = 0; c < 4; c++) {
                accp[0][c] = fmul2(accp[0][c], ff0);
                accp[1][c] = fmul2(accp[1][c], ff1);
            }
        }
        __syncthreads();

        #pragma unroll
        for (int jj = 0; jj < 32; jj++) {
            u64r a01 = *(const u64r*)&Es[jj][ty * 4];
            u64r a23 = *(const u64r*)&Es[jj][ty * 4 + 2];
            #pragma unroll
            for (int c = 0; c < 4; c++) {
                float bvv = Vs[jj][tx * 4 + c];
                u64r bb = pk2(bvv, bvv);
                ffma2(accp[0][c], a01, bb);
                ffma2(accp[1][c], a23, bb);
            }
        }
        __syncthreads();
    }

    #pragma unroll
    for (int off = 1; off < 16; off <<= 1) {
        #pragma unroll
        for (int r = 0; r < 4; r++)
            run_sum[r] += __shfl_xor_sync(0xffffffffu, run_sum[r], off);
    }
    float ov[4][4];
    #pragma unroll
    for (int rp = 0; rp < 2; rp++)
        #pragma unroll
        for (int c = 0; c < 4; c++)
            upk2(accp[rp][c], ov[2 * rp][c], ov[2 * rp + 1][c]);

    int b = bh >> 3, h = bh & 7;
    #pragma unroll
    for (int r = 0; r < 4; r++) {
        int ii = i0 + ty * 4 + r;
        float inv = 1.0f / run_sum[r];
        float4 st;
        #pragma unroll
        for (int c = 0; c < 4; c++) ((float*)&st)[c] = ov[r][c] * inv;
        *(float4*)&d_ao[((size_t)(b * NPOS + ii)) * INNER + h * DHEAD + tx * 4] = st;
    }
}

// ---------------- output GEMM (FFMA2) ----------------
__global__ void k_out(const float* __restrict__ w, const float* __restrict__ ob, float* __restrict__ out) {
    __shared__ float As[32][68];
    __shared__ float Ws[32][68];
    int o0 = blockIdx.x * 64;
    int bi0 = blockIdx.y * 64;
    int tid = threadIdx.x;
    int ty = tid >> 4, tx = tid & 15;
    u64r accp[4][2];
    #pragma unroll
    for (int r = 0; r < 4; r++) { accp[r][0] = 0ull; accp[r][1] = 0ull; }
    for (int c0 = 0; c0 < INNER; c0 += 32) {
        #pragma unroll
        for (int t = 0; t < 8; t++) {
            int idx = tid + t * 256;
            int cc = idx & 31, ii = idx >> 5;
            As[cc][ii] = d_ao[(size_t)(bi0 + ii) * INNER + c0 + cc];
        }
        #pragma unroll
        for (int t = 0; t < 8; t++) {
            int idx = tid + t * 256;
            int cc = idx & 31, o = idx >> 5;
            Ws[cc][o] = w[(o0 + o) * INNER + c0 + cc];
        }
        __syncthreads();
        #pragma unroll
        for (int cc = 0; cc < 32; cc++) {
            u64r a01 = *(const u64r*)&As[cc][ty * 4];
            u64r a23 = *(const u64r*)&As[cc][ty * 4 + 2];
            #pragma unroll
            for (int r = 0; r < 4; r++) {
                float wv = Ws[cc][tx * 4 + r];
                u64r ww = pk2(wv, wv);
                ffma2(accp[r][0], a01, ww);
                ffma2(accp[r][1], a23, ww);
            }
        }
        __syncthreads();
    }
    #pragma unroll
    for (int r = 0; r < 4; r++) {
        int o = o0 + tx * 4 + r;
        float b0v, b1v, b2v, b3v;
        upk2(accp[r][0], b0v, b1v);
        upk2(accp[r][1], b2v, b3v);
        float bv[4] = {b0v, b1v, b2v, b3v};
        float obv = ob[o];
        #pragma unroll
        for (int q = 0; q < 4; q++) {
            int bi = bi0 + ty * 4 + q;
            out[(size_t)bi * DIM + o] = bv[q] + obv;
        }
    }
}

// ---------------- launch ----------------
extern "C" void kernel_launch(void* const* d_in, const int* in_sizes, int n_in,
                              void* d_out, int out_size) {
    const float* x     = (const float*)d_in[0];
    const float* qd_w  = (const float*)d_in[1];
    const float* qd_b  = (const float*)d_in[2];
    const float* q_g   = (const float*)d_in[3];
    const float* q_be  = (const float*)d_in[4];
    const float* qp_w  = (const float*)d_in[5];
    const float* qp_b  = (const float*)d_in[6];
    const float* qm_w  = (const float*)d_in[7];
    const float* qm_b  = (const float*)d_in[8];
    const float* kd_w  = (const float*)d_in[9];
    const float* kd_b  = (const float*)d_in[10];
    const float* k_g   = (const float*)d_in[11];
    const float* k_be  = (const float*)d_in[12];
    const float* kp_w  = (const float*)d_in[13];
    const float* kp_b  = (const float*)d_in[14];
    const float* km_w  = (const float*)d_in[15];
    const float* km_b  = (const float*)d_in[16];
    const float* vd_w  = (const float*)d_in[17];
    const float* vd_b  = (const float*)d_in[18];
    const float* v_g   = (const float*)d_in[19];
    const float* v_be  = (const float*)d_in[20];
    const float* vp_w  = (const float*)d_in[21];
    const float* vp_b  = (const float*)d_in[22];
    const float* out_w = (const float*)d_in[25];
    const float* out_b = (const float*)d_in[26];
    float* out = (float*)d_out;

    k_transpose<<<dim3(32, 8, 4), dim3(32, 8)>>>(x);
    k_meanmax<<<4096, 256>>>(x);
    k_maskconv<<<256, 256>>>(qm_w, qm_b, km_w, km_b);
    k_masktop<<<4096, 256>>>();

    k_sepconv<<<dim3(256, 3), 256>>>(qd_w, qd_b, q_g, q_be,
                                     kd_w, kd_b, k_g, k_be,
                                     vd_w, vd_b, v_g, v_be);
    k_pwgemm<<<dim3(16, 8, 12), 256>>>(qp_w, qp_b, kp_w, kp_b, vp_w, vp_b);

    k_attn<<<dim3(16, 32), 256>>>();
    k_out<<<dim3(4, 64), 256>>>(out_w, out_b, out);
}

// round 14
// speedup vs baseline: 1.1297x; 1.0408x over previous
#include <cuda_runtime.h>
#include <math.h>
#include <math_constants.h>

#define BATCH 4
#define DIM 256
#define IMG 32
#define NPOS 1024
#define HEADS 8
#define DHEAD 64
#define INNER 512
#define BH 32
#define SCALE 0.125f

// ---------------- scratch (device globals; no allocations) ----------------
static __device__ float d_xt[BATCH * DIM * NPOS];
static __device__ float d_xattn[BATCH * 2 * NPOS];
static __device__ float d_qm[BH * NPOS * 2];
static __device__ float d_km[BH * NPOS * 2];
static __device__ float d_mmax[BH * NPOS];
static __device__ float d_msum[BH * NPOS];
static __device__ int   d_top4[BH * NPOS * 4];
static __device__ float d_y[3 * BATCH * DIM * NPOS];
static __device__ float d_qh[BH * NPOS * DHEAD];
static __device__ float d_kh[BH * NPOS * DHEAD];
static __device__ float d_vh[BH * NPOS * DHEAD];
static __device__ float d_ao[BATCH * NPOS * INNER];

#define YSTRIDE (BATCH * DIM * NPOS)

// ---------------- packed f32x2 helpers ----------------
typedef unsigned long long u64r;
__device__ __forceinline__ u64r pk2(float lo, float hi) {
    u64r r; asm("mov.b64 %0, {%1, %2};" : "=l"(r) : "f"(lo), "f"(hi)); return r;
}
__device__ __forceinline__ void upk2(u64r v, float& lo, float& hi) {
    asm("mov.b64 {%0, %1}, %2;" : "=f"(lo), "=f"(hi) : "l"(v));
}
__device__ __forceinline__ void ffma2(u64r& d, u64r a, u64r b) {
    asm("fma.rn.f32x2 %0, %1, %2, %0;" : "+l"(d) : "l"(a), "l"(b));
}
__device__ __forceinline__ u64r fmul2(u64r a, u64r b) {
    u64r r; asm("mul.rn.f32x2 %0, %1, %2;" : "=l"(r) : "l"(a), "l"(b)); return r;
}

__device__ __forceinline__ float mask_logit(float qm0, float qm1, float km0, float km1) {
    return __fmul_rn(__fadd_rn(__fmul_rn(qm0, km0), __fmul_rn(qm1, km1)), SCALE);
}

// strict total order: value desc, index asc (lax.top_k tie-break)
__device__ __forceinline__ bool topgt(float v1, int j1, float v2, int j2) {
    return v1 > v2 || (v1 == v2 && j1 < j2);
}
__device__ __forceinline__ void ce_keepmax(float& va, int& ia, float vb, int ib) {
    bool t = topgt(vb, ib, va, ia);
    va = t ? vb : va; ia = t ? ib : ia;
}
__device__ __forceinline__ void ce_sort(float& va, int& ia, float& vb, int& ib) {
    bool t = topgt(vb, ib, va, ia);
    float v = t ? vb : va; int i = t ? ib : ia;
    vb = t ? va : vb; ib = t ? ia : ib;
    va = v; ia = i;
}

// ---------------- kernel 0: transpose ----------------
__global__ void k_transpose(const float* __restrict__ x) {
    __shared__ float tile[32][33];
    int b = blockIdx.z;
    int p0 = blockIdx.x * 32, c0 = blockIdx.y * 32;
    int tx = threadIdx.x, ty = threadIdx.y;
    #pragma unroll
    for (int r = 0; r < 32; r += 8)
        tile[ty + r][tx] = x[(b * NPOS + p0 + ty + r) * DIM + c0 + tx];
    __syncthreads();
    #pragma unroll
    for (int r = 0; r < 32; r += 8)
        d_xt[(b * DIM + c0 + ty + r) * NPOS + p0 + tx] = tile[tx][ty + r];
}

// ---------------- kernel 1: channel mean/max ----------------
__global__ void k_meanmax(const float* __restrict__ x) {
    int bp = blockIdx.x;
    int b = bp >> 10, p = bp & 1023;
    int tid = threadIdx.x;
    float v = x[(b * NPOS + p) * DIM + tid];
    __shared__ float ss[256], sm[256];
    ss[tid] = v; sm[tid] = v;
    __syncthreads();
    for (int s = 128; s > 0; s >>= 1) {
        if (tid < s) { ss[tid] += ss[tid + s]; sm[tid] = fmaxf(sm[tid], sm[tid + s]); }
        __syncthreads();
    }
    if (tid == 0) {
        d_xattn[b * 2 * NPOS + p] = ss[0] * (1.f / 256.f);
        d_xattn[b * 2 * NPOS + NPOS + p] = sm[0];
    }
}

// ---------------- kernel 2: mask 3x3 convs ----------------
__global__ void k_maskconv(const float* __restrict__ qmw, const float* __restrict__ qmb,
                           const float* __restrict__ kmw, const float* __restrict__ kmb) {
    int idx = blockIdx.x * 256 + threadIdx.x;
    int b = idx >> 14;
    int rem = idx & 16383;
    int oc = rem >> 10;
    int p = rem & 1023;
    int py = p >> 5, px = p & 31;
    float aq = 0.f, ak = 0.f;
    #pragma unroll
    for (int ic = 0; ic < 2; ic++) {
        const float* xa = &d_xattn[(b * 2 + ic) * NPOS];
        #pragma unroll
        for (int ky = 0; ky < 3; ky++) {
            int iy = py + ky - 1;
            if ((unsigned)iy >= 32u) continue;
            #pragma unroll
            for (int kx = 0; kx < 3; kx++) {
                int ix = px + kx - 1;
                if ((unsigned)ix >= 32u) continue;
                float xv = xa[iy * 32 + ix];
                aq = fmaf(xv, qmw[((oc * 2 + ic) * 3 + ky) * 3 + kx], aq);
                ak = fmaf(xv, kmw[((oc * 2 + ic) * 3 + ky) * 3 + kx], ak);
            }
        }
    }
    aq += qmb[oc]; ak += kmb[oc];
    int h = oc >> 1, dd = oc & 1;
    d_qm[((b * HEADS + h) * NPOS + p) * 2 + dd] = aq;
    d_km[((b * HEADS + h) * NPOS + p) * 2 + dd] = ak;
}

// ---------------- kernel 3: warp-per-row mask stats + top-4 ----------------
__global__ void k_masktop() {
    int tid = threadIdx.x;
    int w = tid >> 5, lane = tid & 31;
    int row0 = blockIdx.x * 8;
    int bh = row0 >> 10;
    __shared__ float2 km2[NPOS];
    const float2* kmsrc = (const float2*)&d_km[bh * NPOS * 2];
    #pragma unroll
    for (int t = 0; t < 4; t++) km2[t * 256 + tid] = kmsrc[t * 256 + tid];
    __syncthreads();

    int row = row0 + w;
    float2 q2 = ((const float2*)d_qm)[row];

    float v0 = -CUDART_INF_F, v1 = -CUDART_INF_F, v2 = -CUDART_INF_F, v3 = -CUDART_INF_F;
    int j0i = 0x7fffffff, j1i = 0x7fffffff, j2i = 0x7fffffff, j3i = 0x7fffffff;

    #pragma unroll
    for (int t = 0; t < 32; t++) {
        int j = t * 32 + lane;
        float2 k2 = km2[j];
        float l = mask_logit(q2.x, q2.y, k2.x, k2.y);
        bool g0 = l > v0;
        bool g1 = l > v1;
        bool g2 = l > v2;
        bool g3 = l > v3;
        float nv3 = g3 ? (g2 ? v2 : l) : v3; int nj3 = g3 ? (g2 ? j2i : j) : j3i;
        float nv2 = g2 ? (g1 ? v1 : l) : v2; int nj2 = g2 ? (g1 ? j1i : j) : j2i;
        float nv1 = g1 ? (g0 ? v0 : l) : v1; int nj1 = g1 ? (g0 ? j0i : j) : j1i;
        float nv0 = g0 ? l : v0;             int nj0 = g0 ? j : j0i;
        v0 = nv0; v1 = nv1; v2 = nv2; v3 = nv3;
        j0i = nj0; j1i = nj1; j2i = nj2; j3i = nj3;
    }

    #pragma unroll
    for (int off = 16; off > 0; off >>= 1) {
        float o0 = __shfl_xor_sync(0xffffffffu, v0, off);
        float o1 = __shfl_xor_sync(0xffffffffu, v1, off);
        float o2 = __shfl_xor_sync(0xffffffffu, v2, off);
        float o3 = __shfl_xor_sync(0xffffffffu, v3, off);
        int p0 = __shfl_xor_sync(0xffffffffu, j0i, off);
        int p1 = __shfl_xor_sync(0xffffffffu, j1i, off);
        int p2 = __shfl_xor_sync(0xffffffffu, j2i, off);
        int p3 = __shfl_xor_sync(0xffffffffu, j3i, off);
        ce_keepmax(v0, j0i, o3, p3);
        ce_keepmax(v1, j1i, o2, p2);
        ce_keepmax(v2, j2i, o1, p1);
        ce_keepmax(v3, j3i, o0, p0);
        ce_sort(v0, j0i, v2, j2i);
        ce_sort(v1, j1i, v3, j3i);
        ce_sort(v0, j0i, v1, j1i);
        ce_sort(v2, j2i, v3, j3i);
    }

    float m = v0;
    float s = 0.f;
    #pragma unroll
    for (int t = 0; t < 32; t++) {
        int j = t * 32 + lane;
        float2 k2 = km2[j];
        float l = mask_logit(q2.x, q2.y, k2.x, k2.y);
        s += __expf(l - m);
    }
    #pragma unroll
    for (int off = 16; off > 0; off >>= 1) s += __shfl_xor_sync(0xffffffffu, s, off);

    if (lane == 0) {
        d_mmax[row] = m;
        d_msum[row] = s;
        d_top4[row * 4 + 0] = j0i;
        d_top4[row * 4 + 1] = j1i;
        d_top4[row * 4 + 2] = j2i;
        d_top4[row * 4 + 3] = j3i;
    }
}

// ---------------- fused depthwise conv + BN (batch stats) + GELU ----------------
__global__ void k_sepconv(const float* __restrict__ w0, const float* __restrict__ b0,
                          const float* __restrict__ g0, const float* __restrict__ be0,
                          const float* __restrict__ w1, const float* __restrict__ b1,
                          const float* __restrict__ g1, const float* __restrict__ be1,
                          const float* __restrict__ w2, const float* __restrict__ b2,
                          const float* __restrict__ g2, const float* __restrict__ be2) {
    int c = blockIdx.x, br = blockIdx.y;
    const float* dw  = (br == 0) ? w0 : (br == 1) ? w1 : w2;
    const float* db  = (br == 0) ? b0 : (br == 1) ? b1 : b2;
    const float* gg  = (br == 0) ? g0 : (br == 1) ? g1 : g2;
    const float* bb  = (br == 0) ? be0 : (br == 1) ? be1 : be2;
    int tid = threadIdx.x;
    int lane = tid & 31, wid = tid >> 5;

    __shared__ float xs[BATCH][NPOS];
    __shared__ float w[9];
    __shared__ float bias;
    #pragma unroll
    for (int b = 0; b < BATCH; b++) {
        const float* src = &d_xt[(b * DIM + c) * NPOS];
        #pragma unroll
        for (int t = 0; t < 4; t++) xs[b][t * 256 + tid] = src[t * 256 + tid];
    }
    if (tid < 9) w[tid] = dw[c * 9 + tid];
    if (tid == 9) bias = db[c];
    __syncthreads();

    float vv[16];
    float s1 = 0.f, s2 = 0.f;
    #pragma unroll
    for (int b = 0; b < BATCH; b++) {
        #pragma unroll
        for (int t = 0; t < 4; t++) {
            int p = t * 256 + tid;
            int py = p >> 5, px = p & 31;
            float a = 0.f;
            #pragma unroll
            for (int ky = 0; ky < 3; ky++) {
                int iy = py + ky - 1;
                if ((unsigned)iy >= 32u) continue;
                #pragma unroll
                for (int kx = 0; kx < 3; kx++) {
                    int ix = px + kx - 1;
                    if ((unsigned)ix >= 32u) continue;
                    a = fmaf(xs[b][iy * 32 + ix], w[ky * 3 + kx], a);
                }
            }
            float v = a + bias;
            vv[b * 4 + t] = v;
            s1 += v;
            s2 = fmaf(v, v, s2);
        }
    }

    #pragma unroll
    for (int off = 16; off > 0; off >>= 1) {
        s1 += __shfl_xor_sync(0xffffffffu, s1, off);
        s2 += __shfl_xor_sync(0xffffffffu, s2, off);
    }
    __shared__ float rs1[8], rs2[8];
    if (lane == 0) { rs1[wid] = s1; rs2[wid] = s2; }
    __syncthreads();
    __shared__ float s_mu, s_var;
    if (tid == 0) {
        float a = 0.f, q = 0.f;
        #pragma unroll
        for (int i = 0; i < 8; i++) { a += rs1[i]; q += rs2[i]; }
        float mu = a * (1.f / 4096.f);
        float var = q * (1.f / 4096.f) - mu * mu;
        s_mu = mu;
        s_var = fmaxf(var, 0.f);
    }
    __syncthreads();

    float mu = s_mu, var = s_var;
    float gv = gg[c], bv = bb[c];
    float* dst = &d_y[br * YSTRIDE + c * NPOS];
    #pragma unroll
    for (int b = 0; b < BATCH; b++) {
        #pragma unroll
        for (int t = 0; t < 4; t++) {
            int p = t * 256 + tid;
            float nv = (vv[b * 4 + t] - mu) / sqrtf(var + 1e-5f) * gv + bv;
            float o = 0.5f * nv * (1.0f + erff(nv * 0.70710678118654752f));
            dst[b * DIM * NPOS + p] = o;
        }
    }
}

// ---------------- pointwise 1x1 conv GEMM (FFMA2) ----------------
__global__ void k_pwgemm(const float* __restrict__ w0, const float* __restrict__ bb0,
                         const float* __restrict__ w1, const float* __restrict__ bb1,
                         const float* __restrict__ w2, const float* __restrict__ bb2) {
    __shared__ float As[32][68];
    __shared__ float Ws[32][68];
    int br = blockIdx.z >> 2;
    int b = blockIdx.z & 3;
    const float* w = (br == 0) ? w0 : (br == 1) ? w1 : w2;
    const float* bias = (br == 0) ? bb0 : (br == 1) ? bb1 : bb2;
    float* out = (br == 0) ? d_qh : (br == 1) ? d_kh : d_vh;
    int oc0 = blockIdx.y * 64;
    int i0 = blockIdx.x * 64;
    int tid = threadIdx.x;
    int ty = tid >> 4, tx = tid & 15;
    u64r accp[4][2];
    #pragma unroll
    for (int r = 0; r < 4; r++) { accp[r][0] = 0ull; accp[r][1] = 0ull; }
    for (int c0 = 0; c0 < DIM; c0 += 32) {
        #pragma unroll
        for (int t = 0; t < 8; t++) {
            int idx = tid + t * 256;
            int ii = idx & 63, cc = idx >> 6;
            As[cc][ii] = d_y[br * YSTRIDE + (b * DIM + c0 + cc) * NPOS + i0 + ii];
        }
        #pragma unroll
        for (int t = 0; t < 8; t++) {
            int idx = tid + t * 256;
            int cc = idx & 31, o = idx >> 5;
            Ws[cc][o] = w[(oc0 + o) * DIM + c0 + cc];
        }
        __syncthreads();
        #pragma unroll
        for (int cc = 0; cc < 32; cc++) {
            u64r a01 = *(const u64r*)&As[cc][tx * 4];
            u64r a23 = *(const u64r*)&As[cc][tx * 4 + 2];
            #pragma unroll
            for (int r = 0; r < 4; r++) {
                float wv = Ws[cc][ty * 4 + r];
                u64r ww = pk2(wv, wv);
                ffma2(accp[r][0], a01, ww);
                ffma2(accp[r][1], a23, ww);
            }
        }
        __syncthreads();
    }
    #pragma unroll
    for (int r = 0; r < 4; r++) {
        int oc = oc0 + ty * 4 + r;
        int h = oc >> 6, dd = oc & 63;
        float bbv = bias[oc];
        float c0v, c1v, c2v, c3v;
        upk2(accp[r][0], c0v, c1v);
        upk2(accp[r][1], c2v, c3v);
        float cv[4] = {c0v, c1v, c2v, c3v};
        #pragma unroll
        for (int cq = 0; cq < 4; cq++) {
            int ii = i0 + tx * 4 + cq;
            out[((b * HEADS + h) * NPOS + ii) * DHEAD + dd] = cv[cq] + bbv;
        }
    }
}

// ---------------- fused attention (FFMA2, register-prefetched K/V tiles) ----------------
__global__ void k_attn() {
    __shared__ float Qs[64][68];    // [dd][ii]
    __shared__ float Ks[64][33];    // [dd][jj]
    __shared__ float Vs[32][68];    // [jj][dd]
    __shared__ float Es[32][68];    // [jj][ii]
    __shared__ float s_qm[64][2];
    __shared__ float s_mmax[64];
    __shared__ float s_minv[64];
    __shared__ int   s_top[64][4];

    int i0 = blockIdx.x * 64;
    int bh = blockIdx.y;
    int tid = threadIdx.x;
    int ty = tid >> 4, tx = tid & 15;

    #pragma unroll
    for (int t = 0; t < 16; t++) {
        int idx = tid + t * 256;
        int dd = idx & 63, ii = idx >> 6;
        Qs[dd][ii] = d_qh[(bh * NPOS + i0 + ii) * DHEAD + dd];
    }
    if (tid < 64) {
        int ig = bh * NPOS + i0 + tid;
        s_qm[tid][0] = d_qm[ig * 2];
        s_qm[tid][1] = d_qm[ig * 2 + 1];
        s_mmax[tid] = d_mmax[ig];
        s_minv[tid] = 1.0f / d_msum[ig];
        #pragma unroll
        for (int t = 0; t < 4; t++) s_top[tid][t] = d_top4[ig * 4 + t];
    }
    __syncthreads();

    float run_max[4], run_sum[4];
    #pragma unroll
    for (int r = 0; r < 4; r++) { run_max[r] = -CUDART_INF_F; run_sum[r] = 0.f; }
    u64r accp[2][4];
    #pragma unroll
    for (int c = 0; c < 4; c++) { accp[0][c] = 0ull; accp[1][c] = 0ull; }

    // prefetch tile 0 into registers
    float kreg[8], vreg[8];
    #pragma unroll
    for (int t = 0; t < 8; t++) {
        int idx = tid + t * 256;
        int dd = idx & 63, jj = idx >> 6;
        kreg[t] = d_kh[(bh * NPOS + jj) * DHEAD + dd];
        vreg[t] = d_vh[(bh * NPOS + jj) * DHEAD + dd];
    }

    for (int j0 = 0; j0 < NPOS; j0 += 32) {
        // commit prefetched tile to SMEM
        #pragma unroll
        for (int t = 0; t < 8; t++) {
            int idx = tid + t * 256;
            int dd = idx & 63, jj = idx >> 6;
            Ks[dd][jj] = kreg[t];
            Vs[jj][dd] = vreg[t];
        }
        __syncthreads();

        // prefetch next tile (overlaps with all compute below)
        if (j0 + 32 < NPOS) {
            #pragma unroll
            for (int t = 0; t < 8; t++) {
                int idx = tid + t * 256;
                int dd = idx & 63, jj = idx >> 6;
                kreg[t] = d_kh[(bh * NPOS + j0 + 32 + jj) * DHEAD + dd];
                vreg[t] = d_vh[(bh * NPOS + j0 + 32 + jj) * DHEAD + dd];
            }
        }

        u64r q00 = 0ull, q01 = 0ull, q10 = 0ull, q11 = 0ull;
        #pragma unroll
        for (int dd = 0; dd < 64; dd++) {
            u64r a01 = *(const u64r*)&Qs[dd][ty * 4];
            u64r a23 = *(const u64r*)&Qs[dd][ty * 4 + 2];
            float b0 = Ks[dd][tx * 2];
            float b1 = Ks[dd][tx * 2 + 1];
            u64r bb0 = pk2(b0, b0);
            u64r bb1 = pk2(b1, b1);
            ffma2(q00, a01, bb0);
            ffma2(q01, a01, bb1);
            ffma2(q10, a23, bb0);
            ffma2(q11, a23, bb1);
        }
        float sv[8];
        upk2(q00, sv[0], sv[2]);
        upk2(q01, sv[1], sv[3]);
        upk2(q10, sv[4], sv[6]);
        upk2(q11, sv[5], sv[7]);

        #pragma unroll
        for (int cq = 0; cq < 2; cq++) {
            int jg = j0 + tx * 2 + cq;
            float2 k2 = ((const float2*)d_km)[bh * NPOS + jg];
            #pragma unroll
            for (int r = 0; r < 4; r++) {
                int il = ty * 4 + r;
                float ml = mask_logit(s_qm[il][0], s_qm[il][1], k2.x, k2.y);
                float dprob = __expf(ml - s_mmax[il]) * s_minv[il];
                float oneh = (jg == s_top[il][0] || jg == s_top[il][1] ||
                              jg == s_top[il][2] || jg == s_top[il][3]) ? 1.0f : -100000.0f;
                float maskv = __fadd_rn(__fadd_rn(oneh, -dprob), dprob);
                sv[r * 2 + cq] = __fmul_rn(__fmul_rn(sv[r * 2 + cq], SCALE), maskv);
            }
        }

        float tm[4];
        #pragma unroll
        for (int r = 0; r < 4; r++) tm[r] = fmaxf(sv[r * 2], sv[r * 2 + 1]);
        #pragma unroll
        for (int off = 1; off < 16; off <<= 1) {
            #pragma unroll
            for (int r = 0; r < 4; r++)
                tm[r] = fmaxf(tm[r], __shfl_xor_sync(0xffffffffu, tm[r], off));
        }

        float fr[4];
        #pragma unroll
        for (int r = 0; r < 4; r++) {
            float nm = fmaxf(run_max[r], tm[r]);
            float f = __expf(run_max[r] - nm);
            run_max[r] = nm;
            fr[r] = f;
            float e0 = __expf(sv[r * 2] - nm);
            float e1 = __expf(sv[r * 2 + 1] - nm);
            run_sum[r] = run_sum[r] * f + e0 + e1;
            Es[tx * 2][ty * 4 + r]     = e0;
            Es[tx * 2 + 1][ty * 4 + r] = e1;
        }
        {
            u64r ff0 = pk2(fr[0], fr[1]);
            u64r ff1 = pk2(fr[2], fr[3]);
            #pragma unroll
            for (int c = 0; c < 4; c++) {
                accp[0][c] = fmul2(accp[0][c], ff0);
                accp[1][c] = fmul2(accp[1][c], ff1);
            }
        }
        __syncthreads();

        #pragma unroll
        for (int jj = 0; jj < 32; jj++) {
            u64r a01 = *(const u64r*)&Es[jj][ty * 4];
            u64r a23 = *(const u64r*)&Es[jj][ty * 4 + 2];
            #pragma unroll
            for (int c = 0; c < 4; c++) {
                float bvv = Vs[jj][tx * 4 + c];
                u64r bb = pk2(bvv, bvv);
                ffma2(accp[0][c], a01, bb);
                ffma2(accp[1][c], a23, bb);
            }
        }
        __syncthreads();
    }

    #pragma unroll
    for (int off = 1; off < 16; off <<= 1) {
        #pragma unroll
        for (int r = 0; r < 4; r++)
            run_sum[r] += __shfl_xor_sync(0xffffffffu, run_sum[r], off);
    }
    float ov[4][4];
    #pragma unroll
    for (int rp = 0; rp < 2; rp++)
        #pragma unroll
        for (int c = 0; c < 4; c++)
            upk2(accp[rp][c], ov[2 * rp][c], ov[2 * rp + 1][c]);

    int b = bh >> 3, h = bh & 7;
    #pragma unroll
    for (int r = 0; r < 4; r++) {
        int ii = i0 + ty * 4 + r;
        float inv = 1.0f / run_sum[r];
        float4 st;
        #pragma unroll
        for (int c = 0; c < 4; c++) ((float*)&st)[c] = ov[r][c] * inv;
        *(float4*)&d_ao[((size_t)(b * NPOS + ii)) * INNER + h * DHEAD + tx * 4] = st;
    }
}

// ---------------- output GEMM (FFMA2) ----------------
__global__ void k_out(const float* __restrict__ w, const float* __restrict__ ob, float* __restrict__ out) {
    __shared__ float As[32][68];
    __shared__ float Ws[32][68];
    int o0 = blockIdx.x * 64;
    int bi0 = blockIdx.y * 64;
    int tid = threadIdx.x;
    int ty = tid >> 4, tx = tid & 15;
    u64r accp[4][2];
    #pragma unroll
    for (int r = 0; r < 4; r++) { accp[r][0] = 0ull; accp[r][1] = 0ull; }
    for (int c0 = 0; c0 < INNER; c0 += 32) {
        #pragma unroll
        for (int t = 0; t < 8; t++) {
            int idx = tid + t * 256;
            int cc = idx & 31, ii = idx >> 5;
            As[cc][ii] = d_ao[(size_t)(bi0 + ii) * INNER + c0 + cc];
        }
        #pragma unroll
        for (int t = 0; t < 8; t++) {
            int idx = tid + t * 256;
            int cc = idx & 31, o = idx >> 5;
            Ws[cc][o] = w[(o0 + o) * INNER + c0 + cc];
        }
        __syncthreads();
        #pragma unroll
        for (int cc = 0; cc < 32; cc++) {
            u64r a01 = *(const u64r*)&As[cc][ty * 4];
            u64r a23 = *(const u64r*)&As[cc][ty * 4 + 2];
            #pragma unroll
            for (int r = 0; r < 4; r++) {
                float wv = Ws[cc][tx * 4 + r];
                u64r ww = pk2(wv, wv);
                ffma2(accp[r][0], a01, ww);
                ffma2(accp[r][1], a23, ww);
            }
        }
        __syncthreads();
    }
    #pragma unroll
    for (int r = 0; r < 4; r++) {
        int o = o0 + tx * 4 + r;
        float b0v, b1v, b2v, b3v;
        upk2(accp[r][0], b0v, b1v);
        upk2(accp[r][1], b2v, b3v);
        float bv[4] = {b0v, b1v, b2v, b3v};
        float obv = ob[o];
        #pragma unroll
        for (int q = 0; q < 4; q++) {
            int bi = bi0 + ty * 4 + q;
            out[(size_t)bi * DIM + o] = bv[q] + obv;
        }
    }
}

// ---------------- launch ----------------
extern "C" void kernel_launch(void* const* d_in, const int* in_sizes, int n_in,
                              void* d_out, int out_size) {
    const float* x     = (const float*)d_in[0];
    const float* qd_w  = (const float*)d_in[1];
    const float* qd_b  = (const float*)d_in[2];
    const float* q_g   = (const float*)d_in[3];
    const float* q_be  = (const float*)d_in[4];
    const float* qp_w  = (const float*)d_in[5];
    const float* qp_b  = (const float*)d_in[6];
    const float* qm_w  = (const float*)d_in[7];
    const float* qm_b  = (const float*)d_in[8];
    const float* kd_w  = (const float*)d_in[9];
    const float* kd_b  = (const float*)d_in[10];
    const float* k_g   = (const float*)d_in[11];
    const float* k_be  = (const float*)d_in[12];
    const float* kp_w  = (const float*)d_in[13];
    const float* kp_b  = (const float*)d_in[14];
    const float* km_w  = (const float*)d_in[15];
    const float* km_b  = (const float*)d_in[16];
    const float* vd_w  = (const float*)d_in[17];
    const float* vd_b  = (const float*)d_in[18];
    const float* v_g   = (const float*)d_in[19];
    const float* v_be  = (const float*)d_in[20];
    const float* vp_w  = (const float*)d_in[21];
    const float* vp_b  = (const float*)d_in[22];
    const float* out_w = (const float*)d_in[25];
    const float* out_b = (const float*)d_in[26];
    float* out = (float*)d_out;

    k_transpose<<<dim3(32, 8, 4), dim3(32, 8)>>>(x);
    k_meanmax<<<4096, 256>>>(x);
    k_maskconv<<<256, 256>>>(qm_w, qm_b, km_w, km_b);
    k_masktop<<<4096, 256>>>();

    k_sepconv<<<dim3(256, 3), 256>>>(qd_w, qd_b, q_g, q_be,
                                     kd_w, kd_b, k_g, k_be,
                                     vd_w, vd_b, v_g, v_be);
    k_pwgemm<<<dim3(16, 8, 12), 256>>>(qp_w, qp_b, kp_w, kp_b, vp_w, vp_b);

    k_attn<<<dim3(16, 32), 256>>>();
    k_out<<<dim3(4, 64), 256>>>(out_w, out_b, out);
}

// round 15
// speedup vs baseline: 1.1324x; 1.0024x over previous
#include <cuda_runtime.h>
#include <math.h>
#include <math_constants.h>

#define BATCH 4
#define DIM 256
#define IMG 32
#define NPOS 1024
#define HEADS 8
#define DHEAD 64
#define INNER 512
#define BH 32
#define SCALE 0.125f

// ---------------- scratch (device globals; no allocations) ----------------
static __device__ float d_xt[BATCH * DIM * NPOS];
static __device__ float d_xattn[BATCH * 2 * NPOS];
static __device__ float d_qm[BH * NPOS * 2];
static __device__ float d_km[BH * NPOS * 2];
static __device__ float d_mmax[BH * NPOS];
static __device__ float d_msum[BH * NPOS];
static __device__ int   d_top4[BH * NPOS * 4];
static __device__ float d_y[3 * BATCH * DIM * NPOS];
static __device__ float d_qh[BH * NPOS * DHEAD];
static __device__ float d_kh[BH * NPOS * DHEAD];
static __device__ float d_vh[BH * NPOS * DHEAD];
static __device__ float d_ao[BATCH * NPOS * INNER];

#define YSTRIDE (BATCH * DIM * NPOS)

// ---------------- packed f32x2 helpers ----------------
typedef unsigned long long u64r;
__device__ __forceinline__ u64r pk2(float lo, float hi) {
    u64r r; asm("mov.b64 %0, {%1, %2};" : "=l"(r) : "f"(lo), "f"(hi)); return r;
}
__device__ __forceinline__ void upk2(u64r v, float& lo, float& hi) {
    asm("mov.b64 {%0, %1}, %2;" : "=f"(lo), "=f"(hi) : "l"(v));
}
__device__ __forceinline__ void ffma2(u64r& d, u64r a, u64r b) {
    asm("fma.rn.f32x2 %0, %1, %2, %0;" : "+l"(d) : "l"(a), "l"(b));
}
__device__ __forceinline__ u64r fmul2(u64r a, u64r b) {
    u64r r; asm("mul.rn.f32x2 %0, %1, %2;" : "=l"(r) : "l"(a), "l"(b)); return r;
}

__device__ __forceinline__ float mask_logit(float qm0, float qm1, float km0, float km1) {
    return __fmul_rn(__fadd_rn(__fmul_rn(qm0, km0), __fmul_rn(qm1, km1)), SCALE);
}

// strict total order: value desc, index asc (lax.top_k tie-break)
__device__ __forceinline__ bool topgt(float v1, int j1, float v2, int j2) {
    return v1 > v2 || (v1 == v2 && j1 < j2);
}
__device__ __forceinline__ void ce_keepmax(float& va, int& ia, float vb, int ib) {
    bool t = topgt(vb, ib, va, ia);
    va = t ? vb : va; ia = t ? ib : ia;
}
__device__ __forceinline__ void ce_sort(float& va, int& ia, float& vb, int& ib) {
    bool t = topgt(vb, ib, va, ia);
    float v = t ? vb : va; int i = t ? ib : ia;
    vb = t ? va : vb; ib = t ? ia : ib;
    va = v; ia = i;
}

// ---------------- kernel 0: transpose ----------------
__global__ void k_transpose(const float* __restrict__ x) {
    __shared__ float tile[32][33];
    int b = blockIdx.z;
    int p0 = blockIdx.x * 32, c0 = blockIdx.y * 32;
    int tx = threadIdx.x, ty = threadIdx.y;
    #pragma unroll
    for (int r = 0; r < 32; r += 8)
        tile[ty + r][tx] = x[(b * NPOS + p0 + ty + r) * DIM + c0 + tx];
    __syncthreads();
    #pragma unroll
    for (int r = 0; r < 32; r += 8)
        d_xt[(b * DIM + c0 + ty + r) * NPOS + p0 + tx] = tile[tx][ty + r];
}

// ---------------- kernel 1: channel mean/max ----------------
__global__ void k_meanmax(const float* __restrict__ x) {
    int bp = blockIdx.x;
    int b = bp >> 10, p = bp & 1023;
    int tid = threadIdx.x;
    float v = x[(b * NPOS + p) * DIM + tid];
    __shared__ float ss[256], sm[256];
    ss[tid] = v; sm[tid] = v;
    __syncthreads();
    for (int s = 128; s > 0; s >>= 1) {
        if (tid < s) { ss[tid] += ss[tid + s]; sm[tid] = fmaxf(sm[tid], sm[tid + s]); }
        __syncthreads();
    }
    if (tid == 0) {
        d_xattn[b * 2 * NPOS + p] = ss[0] * (1.f / 256.f);
        d_xattn[b * 2 * NPOS + NPOS + p] = sm[0];
    }
}

// ---------------- kernel 2: mask 3x3 convs ----------------
__global__ void k_maskconv(const float* __restrict__ qmw, const float* __restrict__ qmb,
                           const float* __restrict__ kmw, const float* __restrict__ kmb) {
    int idx = blockIdx.x * 256 + threadIdx.x;
    int b = idx >> 14;
    int rem = idx & 16383;
    int oc = rem >> 10;
    int p = rem & 1023;
    int py = p >> 5, px = p & 31;
    float aq = 0.f, ak = 0.f;
    #pragma unroll
    for (int ic = 0; ic < 2; ic++) {
        const float* xa = &d_xattn[(b * 2 + ic) * NPOS];
        #pragma unroll
        for (int ky = 0; ky < 3; ky++) {
            int iy = py + ky - 1;
            if ((unsigned)iy >= 32u) continue;
            #pragma unroll
            for (int kx = 0; kx < 3; kx++) {
                int ix = px + kx - 1;
                if ((unsigned)ix >= 32u) continue;
                float xv = xa[iy * 32 + ix];
                aq = fmaf(xv, qmw[((oc * 2 + ic) * 3 + ky) * 3 + kx], aq);
                ak = fmaf(xv, kmw[((oc * 2 + ic) * 3 + ky) * 3 + kx], ak);
            }
        }
    }
    aq += qmb[oc]; ak += kmb[oc];
    int h = oc >> 1, dd = oc & 1;
    d_qm[((b * HEADS + h) * NPOS + p) * 2 + dd] = aq;
    d_km[((b * HEADS + h) * NPOS + p) * 2 + dd] = ak;
}

// ---------------- kernel 3: warp-per-row mask stats + top-4 ----------------
__global__ void k_masktop() {
    int tid = threadIdx.x;
    int w = tid >> 5, lane = tid & 31;
    int row0 = blockIdx.x * 8;
    int bh = row0 >> 10;
    __shared__ float2 km2[NPOS];
    const float2* kmsrc = (const float2*)&d_km[bh * NPOS * 2];
    #pragma unroll
    for (int t = 0; t < 4; t++) km2[t * 256 + tid] = kmsrc[t * 256 + tid];
    __syncthreads();

    int row = row0 + w;
    float2 q2 = ((const float2*)d_qm)[row];

    float v0 = -CUDART_INF_F, v1 = -CUDART_INF_F, v2 = -CUDART_INF_F, v3 = -CUDART_INF_F;
    int j0i = 0x7fffffff, j1i = 0x7fffffff, j2i = 0x7fffffff, j3i = 0x7fffffff;

    #pragma unroll
    for (int t = 0; t < 32; t++) {
        int j = t * 32 + lane;
        float2 k2 = km2[j];
        float l = mask_logit(q2.x, q2.y, k2.x, k2.y);
        bool g0 = l > v0;
        bool g1 = l > v1;
        bool g2 = l > v2;
        bool g3 = l > v3;
        float nv3 = g3 ? (g2 ? v2 : l) : v3; int nj3 = g3 ? (g2 ? j2i : j) : j3i;
        float nv2 = g2 ? (g1 ? v1 : l) : v2; int nj2 = g2 ? (g1 ? j1i : j) : j2i;
        float nv1 = g1 ? (g0 ? v0 : l) : v1; int nj1 = g1 ? (g0 ? j0i : j) : j1i;
        float nv0 = g0 ? l : v0;             int nj0 = g0 ? j : j0i;
        v0 = nv0; v1 = nv1; v2 = nv2; v3 = nv3;
        j0i = nj0; j1i = nj1; j2i = nj2; j3i = nj3;
    }

    #pragma unroll
    for (int off = 16; off > 0; off >>= 1) {
        float o0 = __shfl_xor_sync(0xffffffffu, v0, off);
        float o1 = __shfl_xor_sync(0xffffffffu, v1, off);
        float o2 = __shfl_xor_sync(0xffffffffu, v2, off);
        float o3 = __shfl_xor_sync(0xffffffffu, v3, off);
        int p0 = __shfl_xor_sync(0xffffffffu, j0i, off);
        int p1 = __shfl_xor_sync(0xffffffffu, j1i, off);
        int p2 = __shfl_xor_sync(0xffffffffu, j2i, off);
        int p3 = __shfl_xor_sync(0xffffffffu, j3i, off);
        ce_keepmax(v0, j0i, o3, p3);
        ce_keepmax(v1, j1i, o2, p2);
        ce_keepmax(v2, j2i, o1, p1);
        ce_keepmax(v3, j3i, o0, p0);
        ce_sort(v0, j0i, v2, j2i);
        ce_sort(v1, j1i, v3, j3i);
        ce_sort(v0, j0i, v1, j1i);
        ce_sort(v2, j2i, v3, j3i);
    }

    float m = v0;
    float s = 0.f;
    #pragma unroll
    for (int t = 0; t < 32; t++) {
        int j = t * 32 + lane;
        float2 k2 = km2[j];
        float l = mask_logit(q2.x, q2.y, k2.x, k2.y);
        s += __expf(l - m);
    }
    #pragma unroll
    for (int off = 16; off > 0; off >>= 1) s += __shfl_xor_sync(0xffffffffu, s, off);

    if (lane == 0) {
        d_mmax[row] = m;
        d_msum[row] = s;
        d_top4[row * 4 + 0] = j0i;
        d_top4[row * 4 + 1] = j1i;
        d_top4[row * 4 + 2] = j2i;
        d_top4[row * 4 + 3] = j3i;
    }
}

// ---------------- fused depthwise conv + BN (batch stats) + GELU ----------------
__global__ void k_sepconv(const float* __restrict__ w0, const float* __restrict__ b0,
                          const float* __restrict__ g0, const float* __restrict__ be0,
                          const float* __restrict__ w1, const float* __restrict__ b1,
                          const float* __restrict__ g1, const float* __restrict__ be1,
                          const float* __restrict__ w2, const float* __restrict__ b2,
                          const float* __restrict__ g2, const float* __restrict__ be2) {
    int c = blockIdx.x, br = blockIdx.y;
    const float* dw  = (br == 0) ? w0 : (br == 1) ? w1 : w2;
    const float* db  = (br == 0) ? b0 : (br == 1) ? b1 : b2;
    const float* gg  = (br == 0) ? g0 : (br == 1) ? g1 : g2;
    const float* bb  = (br == 0) ? be0 : (br == 1) ? be1 : be2;
    int tid = threadIdx.x;
    int lane = tid & 31, wid = tid >> 5;

    __shared__ float xs[BATCH][NPOS];
    __shared__ float w[9];
    __shared__ float bias;
    #pragma unroll
    for (int b = 0; b < BATCH; b++) {
        const float* src = &d_xt[(b * DIM + c) * NPOS];
        #pragma unroll
        for (int t = 0; t < 4; t++) xs[b][t * 256 + tid] = src[t * 256 + tid];
    }
    if (tid < 9) w[tid] = dw[c * 9 + tid];
    if (tid == 9) bias = db[c];
    __syncthreads();

    float vv[16];
    float s1 = 0.f, s2 = 0.f;
    #pragma unroll
    for (int b = 0; b < BATCH; b++) {
        #pragma unroll
        for (int t = 0; t < 4; t++) {
            int p = t * 256 + tid;
            int py = p >> 5, px = p & 31;
            float a = 0.f;
            #pragma unroll
            for (int ky = 0; ky < 3; ky++) {
                int iy = py + ky - 1;
                if ((unsigned)iy >= 32u) continue;
                #pragma unroll
                for (int kx = 0; kx < 3; kx++) {
                    int ix = px + kx - 1;
                    if ((unsigned)ix >= 32u) continue;
                    a = fmaf(xs[b][iy * 32 + ix], w[ky * 3 + kx], a);
                }
            }
            float v = a + bias;
            vv[b * 4 + t] = v;
            s1 += v;
            s2 = fmaf(v, v, s2);
        }
    }

    #pragma unroll
    for (int off = 16; off > 0; off >>= 1) {
        s1 += __shfl_xor_sync(0xffffffffu, s1, off);
        s2 += __shfl_xor_sync(0xffffffffu, s2, off);
    }
    __shared__ float rs1[8], rs2[8];
    if (lane == 0) { rs1[wid] = s1; rs2[wid] = s2; }
    __syncthreads();
    __shared__ float s_mu, s_var;
    if (tid == 0) {
        float a = 0.f, q = 0.f;
        #pragma unroll
        for (int i = 0; i < 8; i++) { a += rs1[i]; q += rs2[i]; }
        float mu = a * (1.f / 4096.f);
        float var = q * (1.f / 4096.f) - mu * mu;
        s_mu = mu;
        s_var = fmaxf(var, 0.f);
    }
    __syncthreads();

    float mu = s_mu, var = s_var;
    float gv = gg[c], bv = bb[c];
    float* dst = &d_y[br * YSTRIDE + c * NPOS];
    #pragma unroll
    for (int b = 0; b < BATCH; b++) {
        #pragma unroll
        for (int t = 0; t < 4; t++) {
            int p = t * 256 + tid;
            float nv = (vv[b * 4 + t] - mu) / sqrtf(var + 1e-5f) * gv + bv;
            float o = 0.5f * nv * (1.0f + erff(nv * 0.70710678118654752f));
            dst[b * DIM * NPOS + p] = o;
        }
    }
}

// ---------------- pointwise 1x1 conv GEMM (FFMA2, prefetched k-tiles) ----------------
__global__ void k_pwgemm(const float* __restrict__ w0, const float* __restrict__ bb0,
                         const float* __restrict__ w1, const float* __restrict__ bb1,
                         const float* __restrict__ w2, const float* __restrict__ bb2) {
    __shared__ float As[32][68];
    __shared__ float Ws[32][68];
    int br = blockIdx.z >> 2;
    int b = blockIdx.z & 3;
    const float* w = (br == 0) ? w0 : (br == 1) ? w1 : w2;
    const float* bias = (br == 0) ? bb0 : (br == 1) ? bb1 : bb2;
    float* out = (br == 0) ? d_qh : (br == 1) ? d_kh : d_vh;
    int oc0 = blockIdx.y * 64;
    int i0 = blockIdx.x * 64;
    int tid = threadIdx.x;
    int ty = tid >> 4, tx = tid & 15;
    u64r accp[4][2];
    #pragma unroll
    for (int r = 0; r < 4; r++) { accp[r][0] = 0ull; accp[r][1] = 0ull; }

    // prefetch k-tile 0
    float areg[8], wreg[8];
    #pragma unroll
    for (int t = 0; t < 8; t++) {
        int idx = tid + t * 256;
        int ii = idx & 63, cc = idx >> 6;
        areg[t] = d_y[br * YSTRIDE + (b * DIM + cc) * NPOS + i0 + ii];
        int cc2 = idx & 31, o = idx >> 5;
        wreg[t] = w[(oc0 + o) * DIM + cc2];
    }

    for (int c0 = 0; c0 < DIM; c0 += 32) {
        #pragma unroll
        for (int t = 0; t < 8; t++) {
            int idx = tid + t * 256;
            int ii = idx & 63, cc = idx >> 6;
            As[cc][ii] = areg[t];
            int cc2 = idx & 31, o = idx >> 5;
            Ws[cc2][o] = wreg[t];
        }
        __syncthreads();
        if (c0 + 32 < DIM) {
            #pragma unroll
            for (int t = 0; t < 8; t++) {
                int idx = tid + t * 256;
                int ii = idx & 63, cc = idx >> 6;
                areg[t] = d_y[br * YSTRIDE + (b * DIM + c0 + 32 + cc) * NPOS + i0 + ii];
                int cc2 = idx & 31, o = idx >> 5;
                wreg[t] = w[(oc0 + o) * DIM + c0 + 32 + cc2];
            }
        }
        #pragma unroll
        for (int cc = 0; cc < 32; cc++) {
            u64r a01 = *(const u64r*)&As[cc][tx * 4];
            u64r a23 = *(const u64r*)&As[cc][tx * 4 + 2];
            #pragma unroll
            for (int r = 0; r < 4; r++) {
                float wv = Ws[cc][ty * 4 + r];
                u64r ww = pk2(wv, wv);
                ffma2(accp[r][0], a01, ww);
                ffma2(accp[r][1], a23, ww);
            }
        }
        __syncthreads();
    }
    #pragma unroll
    for (int r = 0; r < 4; r++) {
        int oc = oc0 + ty * 4 + r;
        int h = oc >> 6, dd = oc & 63;
        float bbv = bias[oc];
        float c0v, c1v, c2v, c3v;
        upk2(accp[r][0], c0v, c1v);
        upk2(accp[r][1], c2v, c3v);
        float cv[4] = {c0v, c1v, c2v, c3v};
        #pragma unroll
        for (int cq = 0; cq < 4; cq++) {
            int ii = i0 + tx * 4 + cq;
            out[((b * HEADS + h) * NPOS + ii) * DHEAD + dd] = cv[cq] + bbv;
        }
    }
}

// ---------------- fused attention (FFMA2, register-prefetched K/V tiles) ----------------
__global__ void k_attn() {
    __shared__ float Qs[64][68];    // [dd][ii]
    __shared__ float Ks[64][33];    // [dd][jj]
    __shared__ float Vs[32][68];    // [jj][dd]
    __shared__ float Es[32][68];    // [jj][ii]
    __shared__ float s_qm[64][2];
    __shared__ float s_mmax[64];
    __shared__ float s_minv[64];
    __shared__ int   s_top[64][4];

    int i0 = blockIdx.x * 64;
    int bh = blockIdx.y;
    int tid = threadIdx.x;
    int ty = tid >> 4, tx = tid & 15;

    #pragma unroll
    for (int t = 0; t < 16; t++) {
        int idx = tid + t * 256;
        int dd = idx & 63, ii = idx >> 6;
        Qs[dd][ii] = d_qh[(bh * NPOS + i0 + ii) * DHEAD + dd];
    }
    if (tid < 64) {
        int ig = bh * NPOS + i0 + tid;
        s_qm[tid][0] = d_qm[ig * 2];
        s_qm[tid][1] = d_qm[ig * 2 + 1];
        s_mmax[tid] = d_mmax[ig];
        s_minv[tid] = 1.0f / d_msum[ig];
        #pragma unroll
        for (int t = 0; t < 4; t++) s_top[tid][t] = d_top4[ig * 4 + t];
    }
    __syncthreads();

    float run_max[4], run_sum[4];
    #pragma unroll
    for (int r = 0; r < 4; r++) { run_max[r] = -CUDART_INF_F; run_sum[r] = 0.f; }
    u64r accp[2][4];
    #pragma unroll
    for (int c = 0; c < 4; c++) { accp[0][c] = 0ull; accp[1][c] = 0ull; }

    // prefetch tile 0 into registers
    float kreg[8], vreg[8];
    #pragma unroll
    for (int t = 0; t < 8; t++) {
        int idx = tid + t * 256;
        int dd = idx & 63, jj = idx >> 6;
        kreg[t] = d_kh[(bh * NPOS + jj) * DHEAD + dd];
        vreg[t] = d_vh[(bh * NPOS + jj) * DHEAD + dd];
    }

    for (int j0 = 0; j0 < NPOS; j0 += 32) {
        #pragma unroll
        for (int t = 0; t < 8; t++) {
            int idx = tid + t * 256;
            int dd = idx & 63, jj = idx >> 6;
            Ks[dd][jj] = kreg[t];
            Vs[jj][dd] = vreg[t];
        }
        __syncthreads();

        if (j0 + 32 < NPOS) {
            #pragma unroll
            for (int t = 0; t < 8; t++) {
                int idx = tid + t * 256;
                int dd = idx & 63, jj = idx >> 6;
                kreg[t] = d_kh[(bh * NPOS + j0 + 32 + jj) * DHEAD + dd];
                vreg[t] = d_vh[(bh * NPOS + j0 + 32 + jj) * DHEAD + dd];
            }
        }

        u64r q00 = 0ull, q01 = 0ull, q10 = 0ull, q11 = 0ull;
        #pragma unroll
        for (int dd = 0; dd < 64; dd++) {
            u64r a01 = *(const u64r*)&Qs[dd][ty * 4];
            u64r a23 = *(const u64r*)&Qs[dd][ty * 4 + 2];
            float b0 = Ks[dd][tx * 2];
            float b1 = Ks[dd][tx * 2 + 1];
            u64r bb0 = pk2(b0, b0);
            u64r bb1 = pk2(b1, b1);
            ffma2(q00, a01, bb0);
            ffma2(q01, a01, bb1);
            ffma2(q10, a23, bb0);
            ffma2(q11, a23, bb1);
        }
        float sv[8];
        upk2(q00, sv[0], sv[2]);
        upk2(q01, sv[1], sv[3]);
        upk2(q10, sv[4], sv[6]);
        upk2(q11, sv[5], sv[7]);

        #pragma unroll
        for (int cq = 0; cq < 2; cq++) {
            int jg = j0 + tx * 2 + cq;
            float2 k2 = ((const float2*)d_km)[bh * NPOS + jg];
            #pragma unroll
            for (int r = 0; r < 4; r++) {
                int il = ty * 4 + r;
                float ml = mask_logit(s_qm[il][0], s_qm[il][1], k2.x, k2.y);
                float dprob = __expf(ml - s_mmax[il]) * s_minv[il];
                float oneh = (jg == s_top[il][0] || jg == s_top[il][1] ||
                              jg == s_top[il][2] || jg == s_top[il][3]) ? 1.0f : -100000.0f;
                float maskv = __fadd_rn(__fadd_rn(oneh, -dprob), dprob);
                sv[r * 2 + cq] = __fmul_rn(__fmul_rn(sv[r * 2 + cq], SCALE), maskv);
            }
        }

        float tm[4];
        #pragma unroll
        for (int r = 0; r < 4; r++) tm[r] = fmaxf(sv[r * 2], sv[r * 2 + 1]);
        #pragma unroll
        for (int off = 1; off < 16; off <<= 1) {
            #pragma unroll
            for (int r = 0; r < 4; r++)
                tm[r] = fmaxf(tm[r], __shfl_xor_sync(0xffffffffu, tm[r], off));
        }

        float fr[4];
        #pragma unroll
        for (int r = 0; r < 4; r++) {
            float nm = fmaxf(run_max[r], tm[r]);
            float f = __expf(run_max[r] - nm);
            run_max[r] = nm;
            fr[r] = f;
            float e0 = __expf(sv[r * 2] - nm);
            float e1 = __expf(sv[r * 2 + 1] - nm);
            run_sum[r] = run_sum[r] * f + e0 + e1;
            Es[tx * 2][ty * 4 + r]     = e0;
            Es[tx * 2 + 1][ty * 4 + r] = e1;
        }
        {
            u64r ff0 = pk2(fr[0], fr[1]);
            u64r ff1 = pk2(fr[2], fr[3]);
            #pragma unroll
            for (int c = 0; c < 4; c++) {
                accp[0][c] = fmul2(accp[0][c], ff0);
                accp[1][c] = fmul2(accp[1][c], ff1);
            }
        }
        __syncthreads();

        #pragma unroll
        for (int jj = 0; jj < 32; jj++) {
            u64r a01 = *(const u64r*)&Es[jj][ty * 4];
            u64r a23 = *(const u64r*)&Es[jj][ty * 4 + 2];
            #pragma unroll
            for (int c = 0; c < 4; c++) {
                float bvv = Vs[jj][tx * 4 + c];
                u64r bb = pk2(bvv, bvv);
                ffma2(accp[0][c], a01, bb);
                ffma2(accp[1][c], a23, bb);
            }
        }
        __syncthreads();
    }

    #pragma unroll
    for (int off = 1; off < 16; off <<= 1) {
        #pragma unroll
        for (int r = 0; r < 4; r++)
            run_sum[r] += __shfl_xor_sync(0xffffffffu, run_sum[r], off);
    }
    float ov[4][4];
    #pragma unroll
    for (int rp = 0; rp < 2; rp++)
        #pragma unroll
        for (int c = 0; c < 4; c++)
            upk2(accp[rp][c], ov[2 * rp][c], ov[2 * rp + 1][c]);

    int b = bh >> 3, h = bh & 7;
    #pragma unroll
    for (int r = 0; r < 4; r++) {
        int ii = i0 + ty * 4 + r;
        float inv = 1.0f / run_sum[r];
        float4 st;
        #pragma unroll
        for (int c = 0; c < 4; c++) ((float*)&st)[c] = ov[r][c] * inv;
        *(float4*)&d_ao[((size_t)(b * NPOS + ii)) * INNER + h * DHEAD + tx * 4] = st;
    }
}

// ---------------- output GEMM (FFMA2, prefetched k-tiles) ----------------
__global__ void k_out(const float* __restrict__ w, const float* __restrict__ ob, float* __restrict__ out) {
    __shared__ float As[32][68];
    __shared__ float Ws[32][68];
    int o0 = blockIdx.x * 64;
    int bi0 = blockIdx.y * 64;
    int tid = threadIdx.x;
    int ty = tid >> 4, tx = tid & 15;
    u64r accp[4][2];
    #pragma unroll
    for (int r = 0; r < 4; r++) { accp[r][0] = 0ull; accp[r][1] = 0ull; }

    float areg[8], wreg[8];
    #pragma unroll
    for (int t = 0; t < 8; t++) {
        int idx = tid + t * 256;
        int cc = idx & 31, ii = idx >> 5;
        areg[t] = d_ao[(size_t)(bi0 + ii) * INNER + cc];
        wreg[t] = w[(o0 + ii) * INNER + cc];
    }

    for (int c0 = 0; c0 < INNER; c0 += 32) {
        #pragma unroll
        for (int t = 0; t < 8; t++) {
            int idx = tid + t * 256;
            int cc = idx & 31, ii = idx >> 5;
            As[cc][ii] = areg[t];
            Ws[cc][ii] = wreg[t];
        }
        __syncthreads();
        if (c0 + 32 < INNER) {
            #pragma unroll
            for (int t = 0; t < 8; t++) {
                int idx = tid + t * 256;
                int cc = idx & 31, ii = idx >> 5;
                areg[t] = d_ao[(size_t)(bi0 + ii) * INNER + c0 + 32 + cc];
                wreg[t] = w[(o0 + ii) * INNER + c0 + 32 + cc];
            }
        }
        #pragma unroll
        for (int cc = 0; cc < 32; cc++) {
            u64r a01 = *(const u64r*)&As[cc][ty * 4];
            u64r a23 = *(const u64r*)&As[cc][ty * 4 + 2];
            #pragma unroll
            for (int r = 0; r < 4; r++) {
                float wv = Ws[cc][tx * 4 + r];
                u64r ww = pk2(wv, wv);
                ffma2(accp[r][0], a01, ww);
                ffma2(accp[r][1], a23, ww);
            }
        }
        __syncthreads();
    }
    #pragma unroll
    for (int r = 0; r < 4; r++) {
        int o = o0 + tx * 4 + r;
        float b0v, b1v, b2v, b3v;
        upk2(accp[r][0], b0v, b1v);
        upk2(accp[r][1], b2v, b3v);
        float bv[4] = {b0v, b1v, b2v, b3v};
        float obv = ob[o];
        #pragma unroll
        for (int q = 0; q < 4; q++) {
            int bi = bi0 + ty * 4 + q;
            out[(size_t)bi * DIM + o] = bv[q] + obv;
        }
    }
}

// ---------------- launch ----------------
extern "C" void kernel_launch(void* const* d_in, const int* in_sizes, int n_in,
                              void* d_out, int out_size) {
    const float* x     = (const float*)d_in[0];
    const float* qd_w  = (const float*)d_in[1];
    const float* qd_b  = (const float*)d_in[2];
    const float* q_g   = (const float*)d_in[3];
    const float* q_be  = (const float*)d_in[4];
    const float* qp_w  = (const float*)d_in[5];
    const float* qp_b  = (const float*)d_in[6];
    const float* qm_w  = (const float*)d_in[7];
    const float* qm_b  = (const float*)d_in[8];
    const float* kd_w  = (const float*)d_in[9];
    const float* kd_b  = (const float*)d_in[10];
    const float* k_g   = (const float*)d_in[11];
    const float* k_be  = (const float*)d_in[12];
    const float* kp_w  = (const float*)d_in[13];
    const float* kp_b  = (const float*)d_in[14];
    const float* km_w  = (const float*)d_in[15];
    const float* km_b  = (const float*)d_in[16];
    const float* vd_w  = (const float*)d_in[17];
    const float* vd_b  = (const float*)d_in[18];
    const float* v_g   = (const float*)d_in[19];
    const float* v_be  = (const float*)d_in[20];
    const float* vp_w  = (const float*)d_in[21];
    const float* vp_b  = (const float*)d_in[22];
    const float* out_w = (const float*)d_in[25];
    const float* out_b = (const float*)d_in[26];
    float* out = (float*)d_out;

    k_transpose<<<dim3(32, 8, 4), dim3(32, 8)>>>(x);
    k_meanmax<<<4096, 256>>>(x);
    k_maskconv<<<256, 256>>>(qm_w, qm_b, km_w, km_b);
    k_masktop<<<4096, 256>>>();

    k_sepconv<<<dim3(256, 3), 256>>>(qd_w, qd_b, q_g, q_be,
                                     kd_w, kd_b, k_g, k_be,
                                     vd_w, vd_b, v_g, v_be);
    k_pwgemm<<<dim3(16, 8, 12), 256>>>(qp_w, qp_b, kp_w, kp_b, vp_w, vp_b);

    k_attn<<<dim3(16, 32), 256>>>();
    k_out<<<dim3(4, 64), 256>>>(out_w, out_b, out);
}

// round 16
// speedup vs baseline: 1.1377x; 1.0047x over previous
#include <cuda_runtime.h>
#include <math.h>
#include <math_constants.h>

#define BATCH 4
#define DIM 256
#define IMG 32
#define NPOS 1024
#define HEADS 8
#define DHEAD 64
#define INNER 512
#define BH 32
#define SCALE 0.125f

// ---------------- scratch (device globals; no allocations) ----------------
static __device__ float d_xt[BATCH * DIM * NPOS];
static __device__ float d_xattn[BATCH * 2 * NPOS];
static __device__ float d_qm[BH * NPOS * 2];
static __device__ float d_km[BH * NPOS * 2];
static __device__ float d_mmax[BH * NPOS];
static __device__ float d_msum[BH * NPOS];
static __device__ int   d_top4[BH * NPOS * 4];
static __device__ float d_y[3 * BATCH * DIM * NPOS];
static __device__ float d_qh[BH * NPOS * DHEAD];
static __device__ float d_kh[BH * NPOS * DHEAD];
static __device__ float d_vh[BH * NPOS * DHEAD];
static __device__ float d_ao[BATCH * NPOS * INNER];

#define YSTRIDE (BATCH * DIM * NPOS)

// ---------------- packed f32x2 helpers ----------------
typedef unsigned long long u64r;
__device__ __forceinline__ u64r pk2(float lo, float hi) {
    u64r r; asm("mov.b64 %0, {%1, %2};" : "=l"(r) : "f"(lo), "f"(hi)); return r;
}
__device__ __forceinline__ void upk2(u64r v, float& lo, float& hi) {
    asm("mov.b64 {%0, %1}, %2;" : "=f"(lo), "=f"(hi) : "l"(v));
}
__device__ __forceinline__ void ffma2(u64r& d, u64r a, u64r b) {
    asm("fma.rn.f32x2 %0, %1, %2, %0;" : "+l"(d) : "l"(a), "l"(b));
}
__device__ __forceinline__ u64r fmul2(u64r a, u64r b) {
    u64r r; asm("mul.rn.f32x2 %0, %1, %2;" : "=l"(r) : "l"(a), "l"(b)); return r;
}

__device__ __forceinline__ float mask_logit(float qm0, float qm1, float km0, float km1) {
    return __fmul_rn(__fadd_rn(__fmul_rn(qm0, km0), __fmul_rn(qm1, km1)), SCALE);
}

// strict total order: value desc, index asc (lax.top_k tie-break)
__device__ __forceinline__ bool topgt(float v1, int j1, float v2, int j2) {
    return v1 > v2 || (v1 == v2 && j1 < j2);
}
__device__ __forceinline__ void ce_keepmax(float& va, int& ia, float vb, int ib) {
    bool t = topgt(vb, ib, va, ia);
    va = t ? vb : va; ia = t ? ib : ia;
}
__device__ __forceinline__ void ce_sort(float& va, int& ia, float& vb, int& ib) {
    bool t = topgt(vb, ib, va, ia);
    float v = t ? vb : va; int i = t ? ib : ia;
    vb = t ? va : vb; ib = t ? ia : ib;
    va = v; ia = i;
}

// ---------------- kernel 0: fused transpose + channel mean/max ----------------
// grid (32, 4) = (p-slab, batch); block 256. Loads a 32x256 slab of x once,
// emits the transposed tile AND per-pixel channel mean/max.
__global__ void k_transmean(const float* __restrict__ x) {
    __shared__ float xs[32][257];
    int b = blockIdx.y;
    int p0 = blockIdx.x * 32;
    int tid = threadIdx.x;
    int w = tid >> 5, lane = tid & 31;

    // coalesced load: row pp, all 256 channels
    #pragma unroll 4
    for (int pp = 0; pp < 32; pp++)
        xs[pp][tid] = x[(b * NPOS + p0 + pp) * DIM + tid];
    __syncthreads();

    // mean/max per pixel: warp w handles rows w, w+8, w+16, w+24
    #pragma unroll
    for (int t = 0; t < 4; t++) {
        int row = w + t * 8;
        float s = 0.f, m = -CUDART_INF_F;
        #pragma unroll
        for (int k = 0; k < 8; k++) {
            float v = xs[row][lane + k * 32];
            s += v;
            m = fmaxf(m, v);
        }
        #pragma unroll
        for (int off = 16; off > 0; off >>= 1) {
            s += __shfl_xor_sync(0xffffffffu, s, off);
            m = fmaxf(m, __shfl_xor_sync(0xffffffffu, m, off));
        }
        if (lane == 0) {
            d_xattn[b * 2 * NPOS + p0 + row] = s * (1.f / 256.f);
            d_xattn[b * 2 * NPOS + NPOS + p0 + row] = m;
        }
    }

    // transposed writes: warp w covers channels [w*32, w*32+32)
    #pragma unroll
    for (int k = 0; k < 32; k++) {
        int c = w * 32 + k;
        d_xt[(b * DIM + c) * NPOS + p0 + lane] = xs[lane][c];
    }
}

// ---------------- kernel 2: mask 3x3 convs ----------------
__global__ void k_maskconv(const float* __restrict__ qmw, const float* __restrict__ qmb,
                           const float* __restrict__ kmw, const float* __restrict__ kmb) {
    int idx = blockIdx.x * 256 + threadIdx.x;
    int b = idx >> 14;
    int rem = idx & 16383;
    int oc = rem >> 10;
    int p = rem & 1023;
    int py = p >> 5, px = p & 31;
    float aq = 0.f, ak = 0.f;
    #pragma unroll
    for (int ic = 0; ic < 2; ic++) {
        const float* xa = &d_xattn[(b * 2 + ic) * NPOS];
        #pragma unroll
        for (int ky = 0; ky < 3; ky++) {
            int iy = py + ky - 1;
            if ((unsigned)iy >= 32u) continue;
            #pragma unroll
            for (int kx = 0; kx < 3; kx++) {
                int ix = px + kx - 1;
                if ((unsigned)ix >= 32u) continue;
                float xv = xa[iy * 32 + ix];
                aq = fmaf(xv, qmw[((oc * 2 + ic) * 3 + ky) * 3 + kx], aq);
                ak = fmaf(xv, kmw[((oc * 2 + ic) * 3 + ky) * 3 + kx], ak);
            }
        }
    }
    aq += qmb[oc]; ak += kmb[oc];
    int h = oc >> 1, dd = oc & 1;
    d_qm[((b * HEADS + h) * NPOS + p) * 2 + dd] = aq;
    d_km[((b * HEADS + h) * NPOS + p) * 2 + dd] = ak;
}

// ---------------- kernel 3: warp-per-row mask stats + top-4 ----------------
__global__ void k_masktop() {
    int tid = threadIdx.x;
    int w = tid >> 5, lane = tid & 31;
    int row0 = blockIdx.x * 8;
    int bh = row0 >> 10;
    __shared__ float2 km2[NPOS];
    const float2* kmsrc = (const float2*)&d_km[bh * NPOS * 2];
    #pragma unroll
    for (int t = 0; t < 4; t++) km2[t * 256 + tid] = kmsrc[t * 256 + tid];
    __syncthreads();

    int row = row0 + w;
    float2 q2 = ((const float2*)d_qm)[row];

    float v0 = -CUDART_INF_F, v1 = -CUDART_INF_F, v2 = -CUDART_INF_F, v3 = -CUDART_INF_F;
    int j0i = 0x7fffffff, j1i = 0x7fffffff, j2i = 0x7fffffff, j3i = 0x7fffffff;

    #pragma unroll
    for (int t = 0; t < 32; t++) {
        int j = t * 32 + lane;
        float2 k2 = km2[j];
        float l = mask_logit(q2.x, q2.y, k2.x, k2.y);
        bool g0 = l > v0;
        bool g1 = l > v1;
        bool g2 = l > v2;
        bool g3 = l > v3;
        float nv3 = g3 ? (g2 ? v2 : l) : v3; int nj3 = g3 ? (g2 ? j2i : j) : j3i;
        float nv2 = g2 ? (g1 ? v1 : l) : v2; int nj2 = g2 ? (g1 ? j1i : j) : j2i;
        float nv1 = g1 ? (g0 ? v0 : l) : v1; int nj1 = g1 ? (g0 ? j0i : j) : j1i;
        float nv0 = g0 ? l : v0;             int nj0 = g0 ? j : j0i;
        v0 = nv0; v1 = nv1; v2 = nv2; v3 = nv3;
        j0i = nj0; j1i = nj1; j2i = nj2; j3i = nj3;
    }

    #pragma unroll
    for (int off = 16; off > 0; off >>= 1) {
        float o0 = __shfl_xor_sync(0xffffffffu, v0, off);
        float o1 = __shfl_xor_sync(0xffffffffu, v1, off);
        float o2 = __shfl_xor_sync(0xffffffffu, v2, off);
        float o3 = __shfl_xor_sync(0xffffffffu, v3, off);
        int p0 = __shfl_xor_sync(0xffffffffu, j0i, off);
        int p1 = __shfl_xor_sync(0xffffffffu, j1i, off);
        int p2 = __shfl_xor_sync(0xffffffffu, j2i, off);
        int p3 = __shfl_xor_sync(0xffffffffu, j3i, off);
        ce_keepmax(v0, j0i, o3, p3);
        ce_keepmax(v1, j1i, o2, p2);
        ce_keepmax(v2, j2i, o1, p1);
        ce_keepmax(v3, j3i, o0, p0);
        ce_sort(v0, j0i, v2, j2i);
        ce_sort(v1, j1i, v3, j3i);
        ce_sort(v0, j0i, v1, j1i);
        ce_sort(v2, j2i, v3, j3i);
    }

    float m = v0;
    float s = 0.f;
    #pragma unroll
    for (int t = 0; t < 32; t++) {
        int j = t * 32 + lane;
        float2 k2 = km2[j];
        float l = mask_logit(q2.x, q2.y, k2.x, k2.y);
        s += __expf(l - m);
    }
    #pragma unroll
    for (int off = 16; off > 0; off >>= 1) s += __shfl_xor_sync(0xffffffffu, s, off);

    if (lane == 0) {
        d_mmax[row] = m;
        d_msum[row] = s;
        d_top4[row * 4 + 0] = j0i;
        d_top4[row * 4 + 1] = j1i;
        d_top4[row * 4 + 2] = j2i;
        d_top4[row * 4 + 3] = j3i;
    }
}

// ---------------- fused depthwise conv + BN (batch stats) + GELU ----------------
__global__ void k_sepconv(const float* __restrict__ w0, const float* __restrict__ b0,
                          const float* __restrict__ g0, const float* __restrict__ be0,
                          const float* __restrict__ w1, const float* __restrict__ b1,
                          const float* __restrict__ g1, const float* __restrict__ be1,
                          const float* __restrict__ w2, const float* __restrict__ b2,
                          const float* __restrict__ g2, const float* __restrict__ be2) {
    int c = blockIdx.x, br = blockIdx.y;
    const float* dw  = (br == 0) ? w0 : (br == 1) ? w1 : w2;
    const float* db  = (br == 0) ? b0 : (br == 1) ? b1 : b2;
    const float* gg  = (br == 0) ? g0 : (br == 1) ? g1 : g2;
    const float* bb  = (br == 0) ? be0 : (br == 1) ? be1 : be2;
    int tid = threadIdx.x;
    int lane = tid & 31, wid = tid >> 5;

    __shared__ float xs[BATCH][NPOS];
    __shared__ float w[9];
    __shared__ float bias;
    #pragma unroll
    for (int b = 0; b < BATCH; b++) {
        const float* src = &d_xt[(b * DIM + c) * NPOS];
        #pragma unroll
        for (int t = 0; t < 4; t++) xs[b][t * 256 + tid] = src[t * 256 + tid];
    }
    if (tid < 9) w[tid] = dw[c * 9 + tid];
    if (tid == 9) bias = db[c];
    __syncthreads();

    float vv[16];
    float s1 = 0.f, s2 = 0.f;
    #pragma unroll
    for (int b = 0; b < BATCH; b++) {
        #pragma unroll
        for (int t = 0; t < 4; t++) {
            int p = t * 256 + tid;
            int py = p >> 5, px = p & 31;
            float a = 0.f;
            #pragma unroll
            for (int ky = 0; ky < 3; ky++) {
                int iy = py + ky - 1;
                if ((unsigned)iy >= 32u) continue;
                #pragma unroll
                for (int kx = 0; kx < 3; kx++) {
                    int ix = px + kx - 1;
                    if ((unsigned)ix >= 32u) continue;
                    a = fmaf(xs[b][iy * 32 + ix], w[ky * 3 + kx], a);
                }
            }
            float v = a + bias;
            vv[b * 4 + t] = v;
            s1 += v;
            s2 = fmaf(v, v, s2);
        }
    }

    #pragma unroll
    for (int off = 16; off > 0; off >>= 1) {
        s1 += __shfl_xor_sync(0xffffffffu, s1, off);
        s2 += __shfl_xor_sync(0xffffffffu, s2, off);
    }
    __shared__ float rs1[8], rs2[8];
    if (lane == 0) { rs1[wid] = s1; rs2[wid] = s2; }
    __syncthreads();
    __shared__ float s_mu, s_var;
    if (tid == 0) {
        float a = 0.f, q = 0.f;
        #pragma unroll
        for (int i = 0; i < 8; i++) { a += rs1[i]; q += rs2[i]; }
        float mu = a * (1.f / 4096.f);
        float var = q * (1.f / 4096.f) - mu * mu;
        s_mu = mu;
        s_var = fmaxf(var, 0.f);
    }
    __syncthreads();

    float mu = s_mu, var = s_var;
    float gv = gg[c], bv = bb[c];
    float* dst = &d_y[br * YSTRIDE + c * NPOS];
    #pragma unroll
    for (int b = 0; b < BATCH; b++) {
        #pragma unroll
        for (int t = 0; t < 4; t++) {
            int p = t * 256 + tid;
            float nv = (vv[b * 4 + t] - mu) / sqrtf(var + 1e-5f) * gv + bv;
            float o = 0.5f * nv * (1.0f + erff(nv * 0.70710678118654752f));
            dst[b * DIM * NPOS + p] = o;
        }
    }
}

// ---------------- pointwise 1x1 conv GEMM (FFMA2, prefetched k-tiles) ----------------
__global__ void k_pwgemm(const float* __restrict__ w0, const float* __restrict__ bb0,
                         const float* __restrict__ w1, const float* __restrict__ bb1,
                         const float* __restrict__ w2, const float* __restrict__ bb2) {
    __shared__ float As[32][68];
    __shared__ float Ws[32][68];
    int br = blockIdx.z >> 2;
    int b = blockIdx.z & 3;
    const float* w = (br == 0) ? w0 : (br == 1) ? w1 : w2;
    const float* bias = (br == 0) ? bb0 : (br == 1) ? bb1 : bb2;
    float* out = (br == 0) ? d_qh : (br == 1) ? d_kh : d_vh;
    int oc0 = blockIdx.y * 64;
    int i0 = blockIdx.x * 64;
    int tid = threadIdx.x;
    int ty = tid >> 4, tx = tid & 15;
    u64r accp[4][2];
    #pragma unroll
    for (int r = 0; r < 4; r++) { accp[r][0] = 0ull; accp[r][1] = 0ull; }

    float areg[8], wreg[8];
    #pragma unroll
    for (int t = 0; t < 8; t++) {
        int idx = tid + t * 256;
        int ii = idx & 63, cc = idx >> 6;
        areg[t] = d_y[br * YSTRIDE + (b * DIM + cc) * NPOS + i0 + ii];
        int cc2 = idx & 31, o = idx >> 5;
        wreg[t] = w[(oc0 + o) * DIM + cc2];
    }

    for (int c0 = 0; c0 < DIM; c0 += 32) {
        #pragma unroll
        for (int t = 0; t < 8; t++) {
            int idx = tid + t * 256;
            int ii = idx & 63, cc = idx >> 6;
            As[cc][ii] = areg[t];
            int cc2 = idx & 31, o = idx >> 5;
            Ws[cc2][o] = wreg[t];
        }
        __syncthreads();
        if (c0 + 32 < DIM) {
            #pragma unroll
            for (int t = 0; t < 8; t++) {
                int idx = tid + t * 256;
                int ii = idx & 63, cc = idx >> 6;
                areg[t] = d_y[br * YSTRIDE + (b * DIM + c0 + 32 + cc) * NPOS + i0 + ii];
                int cc2 = idx & 31, o = idx >> 5;
                wreg[t] = w[(oc0 + o) * DIM + c0 + 32 + cc2];
            }
        }
        #pragma unroll
        for (int cc = 0; cc < 32; cc++) {
            u64r a01 = *(const u64r*)&As[cc][tx * 4];
            u64r a23 = *(const u64r*)&As[cc][tx * 4 + 2];
            #pragma unroll
            for (int r = 0; r < 4; r++) {
                float wv = Ws[cc][ty * 4 + r];
                u64r ww = pk2(wv, wv);
                ffma2(accp[r][0], a01, ww);
                ffma2(accp[r][1], a23, ww);
            }
        }
        __syncthreads();
    }
    #pragma unroll
    for (int r = 0; r < 4; r++) {
        int oc = oc0 + ty * 4 + r;
        int h = oc >> 6, dd = oc & 63;
        float bbv = bias[oc];
        float c0v, c1v, c2v, c3v;
        upk2(accp[r][0], c0v, c1v);
        upk2(accp[r][1], c2v, c3v);
        float cv[4] = {c0v, c1v, c2v, c3v};
        #pragma unroll
        for (int cq = 0; cq < 4; cq++) {
            int ii = i0 + tx * 4 + cq;
            out[((b * HEADS + h) * NPOS + ii) * DHEAD + dd] = cv[cq] + bbv;
        }
    }
}

// ---------------- fused attention (FFMA2, register-prefetched K/V tiles) ----------------
__global__ void k_attn() {
    __shared__ float Qs[64][68];    // [dd][ii]
    __shared__ float Ks[64][33];    // [dd][jj]
    __shared__ float Vs[32][68];    // [jj][dd]
    __shared__ float Es[32][68];    // [jj][ii]
    __shared__ float s_qm[64][2];
    __shared__ float s_mmax[64];
    __shared__ float s_minv[64];
    __shared__ int   s_top[64][4];

    int i0 = blockIdx.x * 64;
    int bh = blockIdx.y;
    int tid = threadIdx.x;
    int ty = tid >> 4, tx = tid & 15;

    #pragma unroll
    for (int t = 0; t < 16; t++) {
        int idx = tid + t * 256;
        int dd = idx & 63, ii = idx >> 6;
        Qs[dd][ii] = d_qh[(bh * NPOS + i0 + ii) * DHEAD + dd];
    }
    if (tid < 64) {
        int ig = bh * NPOS + i0 + tid;
        s_qm[tid][0] = d_qm[ig * 2];
        s_qm[tid][1] = d_qm[ig * 2 + 1];
        s_mmax[tid] = d_mmax[ig];
        s_minv[tid] = 1.0f / d_msum[ig];
        #pragma unroll
        for (int t = 0; t < 4; t++) s_top[tid][t] = d_top4[ig * 4 + t];
    }
    __syncthreads();

    float run_max[4], run_sum[4];
    #pragma unroll
    for (int r = 0; r < 4; r++) { run_max[r] = -CUDART_INF_F; run_sum[r] = 0.f; }
    u64r accp[2][4];
    #pragma unroll
    for (int c = 0; c < 4; c++) { accp[0][c] = 0ull; accp[1][c] = 0ull; }

    float kreg[8], vreg[8];
    #pragma unroll
    for (int t = 0; t < 8; t++) {
        int idx = tid + t * 256;
        int dd = idx & 63, jj = idx >> 6;
        kreg[t] = d_kh[(bh * NPOS + jj) * DHEAD + dd];
        vreg[t] = d_vh[(bh * NPOS + jj) * DHEAD + dd];
    }

    for (int j0 = 0; j0 < NPOS; j0 += 32) {
        #pragma unroll
        for (int t = 0; t < 8; t++) {
            int idx = tid + t * 256;
            int dd = idx & 63, jj = idx >> 6;
            Ks[dd][jj] = kreg[t];
            Vs[jj][dd] = vreg[t];
        }
        __syncthreads();

        if (j0 + 32 < NPOS) {
            #pragma unroll
            for (int t = 0; t < 8; t++) {
                int idx = tid + t * 256;
                int dd = idx & 63, jj = idx >> 6;
                kreg[t] = d_kh[(bh * NPOS + j0 + 32 + jj) * DHEAD + dd];
                vreg[t] = d_vh[(bh * NPOS + j0 + 32 + jj) * DHEAD + dd];
            }
        }

        u64r q00 = 0ull, q01 = 0ull, q10 = 0ull, q11 = 0ull;
        #pragma unroll
        for (int dd = 0; dd < 64; dd++) {
            u64r a01 = *(const u64r*)&Qs[dd][ty * 4];
            u64r a23 = *(const u64r*)&Qs[dd][ty * 4 + 2];
            float b0 = Ks[dd][tx * 2];
            float b1 = Ks[dd][tx * 2 + 1];
            u64r bb0 = pk2(b0, b0);
            u64r bb1 = pk2(b1, b1);
            ffma2(q00, a01, bb0);
            ffma2(q01, a01, bb1);
            ffma2(q10, a23, bb0);
            ffma2(q11, a23, bb1);
        }
        float sv[8];
        upk2(q00, sv[0], sv[2]);
        upk2(q01, sv[1], sv[3]);
        upk2(q10, sv[4], sv[6]);
        upk2(q11, sv[5], sv[7]);

        #pragma unroll
        for (int cq = 0; cq < 2; cq++) {
            int jg = j0 + tx * 2 + cq;
            float2 k2 = ((const float2*)d_km)[bh * NPOS + jg];
            #pragma unroll
            for (int r = 0; r < 4; r++) {
                int il = ty * 4 + r;
                float ml = mask_logit(s_qm[il][0], s_qm[il][1], k2.x, k2.y);
                float dprob = __expf(ml - s_mmax[il]) * s_minv[il];
                float oneh = (jg == s_top[il][0] || jg == s_top[il][1] ||
                              jg == s_top[il][2] || jg == s_top[il][3]) ? 1.0f : -100000.0f;
                float maskv = __fadd_rn(__fadd_rn(oneh, -dprob), dprob);
                sv[r * 2 + cq] = __fmul_rn(__fmul_rn(sv[r * 2 + cq], SCALE), maskv);
            }
        }

        float tm[4];
        #pragma unroll
        for (int r = 0; r < 4; r++) tm[r] = fmaxf(sv[r * 2], sv[r * 2 + 1]);
        #pragma unroll
        for (int off = 1; off < 16; off <<= 1) {
            #pragma unroll
            for (int r = 0; r < 4; r++)
                tm[r] = fmaxf(tm[r], __shfl_xor_sync(0xffffffffu, tm[r], off));
        }

        float fr[4];
        #pragma unroll
        for (int r = 0; r < 4; r++) {
            float nm = fmaxf(run_max[r], tm[r]);
            float f = __expf(run_max[r] - nm);
            run_max[r] = nm;
            fr[r] = f;
            float e0 = __expf(sv[r * 2] - nm);
            float e1 = __expf(sv[r * 2 + 1] - nm);
            run_sum[r] = run_sum[r] * f + e0 + e1;
            Es[tx * 2][ty * 4 + r]     = e0;
            Es[tx * 2 + 1][ty * 4 + r] = e1;
        }
        {
            u64r ff0 = pk2(fr[0], fr[1]);
            u64r ff1 = pk2(fr[2], fr[3]);
            #pragma unroll
            for (int c = 0; c < 4; c++) {
                accp[0][c] = fmul2(accp[0][c], ff0);
                accp[1][c] = fmul2(accp[1][c], ff1);
            }
        }
        __syncthreads();

        #pragma unroll
        for (int jj = 0; jj < 32; jj++) {
            u64r a01 = *(const u64r*)&Es[jj][ty * 4];
            u64r a23 = *(const u64r*)&Es[jj][ty * 4 + 2];
            #pragma unroll
            for (int c = 0; c < 4; c++) {
                float bvv = Vs[jj][tx * 4 + c];
                u64r bb = pk2(bvv, bvv);
                ffma2(accp[0][c], a01, bb);
                ffma2(accp[1][c], a23, bb);
            }
        }
        __syncthreads();
    }

    #pragma unroll
    for (int off = 1; off < 16; off <<= 1) {
        #pragma unroll
        for (int r = 0; r < 4; r++)
            run_sum[r] += __shfl_xor_sync(0xffffffffu, run_sum[r], off);
    }
    float ov[4][4];
    #pragma unroll
    for (int rp = 0; rp < 2; rp++)
        #pragma unroll
        for (int c = 0; c < 4; c++)
            upk2(accp[rp][c], ov[2 * rp][c], ov[2 * rp + 1][c]);

    int b = bh >> 3, h = bh & 7;
    #pragma unroll
    for (int r = 0; r < 4; r++) {
        int ii = i0 + ty * 4 + r;
        float inv = 1.0f / run_sum[r];
        float4 st;
        #pragma unroll
        for (int c = 0; c < 4; c++) ((float*)&st)[c] = ov[r][c] * inv;
        *(float4*)&d_ao[((size_t)(b * NPOS + ii)) * INNER + h * DHEAD + tx * 4] = st;
    }
}

// ---------------- output GEMM (FFMA2, prefetched k-tiles) ----------------
__global__ void k_out(const float* __restrict__ w, const float* __restrict__ ob, float* __restrict__ out) {
    __shared__ float As[32][68];
    __shared__ float Ws[32][68];
    int o0 = blockIdx.x * 64;
    int bi0 = blockIdx.y * 64;
    int tid = threadIdx.x;
    int ty = tid >> 4, tx = tid & 15;
    u64r accp[4][2];
    #pragma unroll
    for (int r = 0; r < 4; r++) { accp[r][0] = 0ull; accp[r][1] = 0ull; }

    float areg[8], wreg[8];
    #pragma unroll
    for (int t = 0; t < 8; t++) {
        int idx = tid + t * 256;
        int cc = idx & 31, ii = idx >> 5;
        areg[t] = d_ao[(size_t)(bi0 + ii) * INNER + cc];
        wreg[t] = w[(o0 + ii) * INNER + cc];
    }

    for (int c0 = 0; c0 < INNER; c0 += 32) {
        #pragma unroll
        for (int t = 0; t < 8; t++) {
            int idx = tid + t * 256;
            int cc = idx & 31, ii = idx >> 5;
            As[cc][ii] = areg[t];
            Ws[cc][ii] = wreg[t];
        }
        __syncthreads();
        if (c0 + 32 < INNER) {
            #pragma unroll
            for (int t = 0; t < 8; t++) {
                int idx = tid + t * 256;
                int cc = idx & 31, ii = idx >> 5;
                areg[t] = d_ao[(size_t)(bi0 + ii) * INNER + c0 + 32 + cc];
                wreg[t] = w[(o0 + ii) * INNER + c0 + 32 + cc];
            }
        }
        #pragma unroll
        for (int cc = 0; cc < 32; cc++) {
            u64r a01 = *(const u64r*)&As[cc][ty * 4];
            u64r a23 = *(const u64r*)&As[cc][ty * 4 + 2];
            #pragma unroll
            for (int r = 0; r < 4; r++) {
                float wv = Ws[cc][tx * 4 + r];
                u64r ww = pk2(wv, wv);
                ffma2(accp[r][0], a01, ww);
                ffma2(accp[r][1], a23, ww);
            }
        }
        __syncthreads();
    }
    #pragma unroll
    for (int r = 0; r < 4; r++) {
        int o = o0 + tx * 4 + r;
        float b0v, b1v, b2v, b3v;
        upk2(accp[r][0], b0v, b1v);
        upk2(accp[r][1], b2v, b3v);
        float bv[4] = {b0v, b1v, b2v, b3v};
        float obv = ob[o];
        #pragma unroll
        for (int q = 0; q < 4; q++) {
            int bi = bi0 + ty * 4 + q;
            out[(size_t)bi * DIM + o] = bv[q] + obv;
        }
    }
}

// ---------------- launch ----------------
extern "C" void kernel_launch(void* const* d_in, const int* in_sizes, int n_in,
                              void* d_out, int out_size) {
    const float* x     = (const float*)d_in[0];
    const float* qd_w  = (const float*)d_in[1];
    const float* qd_b  = (const float*)d_in[2];
    const float* q_g   = (const float*)d_in[3];
    const float* q_be  = (const float*)d_in[4];
    const float* qp_w  = (const float*)d_in[5];
    const float* qp_b  = (const float*)d_in[6];
    const float* qm_w  = (const float*)d_in[7];
    const float* qm_b  = (const float*)d_in[8];
    const float* kd_w  = (const float*)d_in[9];
    const float* kd_b  = (const float*)d_in[10];
    const float* k_g   = (const float*)d_in[11];
    const float* k_be  = (const float*)d_in[12];
    const float* kp_w  = (const float*)d_in[13];
    const float* kp_b  = (const float*)d_in[14];
    const float* km_w  = (const float*)d_in[15];
    const float* km_b  = (const float*)d_in[16];
    const float* vd_w  = (const float*)d_in[17];
    const float* vd_b  = (const float*)d_in[18];
    const float* v_g   = (const float*)d_in[19];
    const float* v_be  = (const float*)d_in[20];
    const float* vp_w  = (const float*)d_in[21];
    const float* vp_b  = (const float*)d_in[22];
    const float* out_w = (const float*)d_in[25];
    const float* out_b = (const float*)d_in[26];
    float* out = (float*)d_out;

    k_transmean<<<dim3(32, 4), 256>>>(x);
    k_maskconv<<<256, 256>>>(qm_w, qm_b, km_w, km_b);
    k_masktop<<<4096, 256>>>();

    k_sepconv<<<dim3(256, 3), 256>>>(qd_w, qd_b, q_g, q_be,
                                     kd_w, kd_b, k_g, k_be,
                                     vd_w, vd_b, v_g, v_be);
    k_pwgemm<<<dim3(16, 8, 12), 256>>>(qp_w, qp_b, kp_w, kp_b, vp_w, vp_b);

    k_attn<<<dim3(16, 32), 256>>>();
    k_out<<<dim3(4, 64), 256>>>(out_w, out_b, out);
}